// round 15
// baseline (speedup 1.0000x reference)
#include <cuda_runtime.h>
#include <cuda_fp16.h>
#include <cstdint>

// ---------------- problem constants ----------------
#define BT     8
#define NPIX   4096
#define DD     512
#define CFF    128
#define INCC   640
#define GG     64
#define NWIN   64
#define NGLOB  64
#define NHEAD  8
#define DHH    64
#define MTOK   32768

// ---------------- scratch ----------------
__device__ float  g_kg [BT*NGLOB*INCC];
__device__ float  g_vg [BT*NGLOB*DD];
__device__ __half g_xf [MTOK*INCC];
__device__ __half g_qkh[MTOK*INCC];
__device__ __half g_qkn[MTOK*INCC];
__device__ __half g_xn [MTOK*DD];
__device__ __half g_kgn[BT*NGLOB*INCC];
__device__ __half g_vgn[BT*NGLOB*DD];
__device__ __half g_Q  [MTOK*DD];
__device__ __half g_Kl [MTOK*DD];
__device__ __half g_Vl [MTOK*DD];
__device__ __half g_Kg [BT*NGLOB*DD];
__device__ __half g_Vg [BT*NGLOB*DD];
__device__ __half g_O  [MTOK*DD];
__device__ __half g_fwqk[2*DD*INCC];
__device__ float  g_fbqk[2*DD];
__device__ __half g_fwv[DD*DD];
__device__ __half g_fwo[DD*DD];
__device__ __half g_frw[INCC*INCC];
__device__ float  g_fbv[DD];
__device__ float  g_cvT[64*DD];
__device__ float  g_ckT[64*INCC];

// ---------------- helpers ----------------
__device__ __forceinline__ int win_map(int r) {
    int b = r >> 12;
    int p = r & 4095;
    int h = p >> 6, w = p & 63;
    int g = ((h >> 3) << 3) | (w >> 3);
    int n = ((h & 7) << 3) | (w & 7);
    return (((b << 6) | g) << 6) | n;
}

__device__ __forceinline__ uint32_t h2b(float a, float b) {
    __half2 h = __floats2half2_rn(a, b);
    return *(uint32_t*)&h;
}
__device__ __forceinline__ uint32_t h2ex2(uint32_t t) {
    uint32_t d;
    asm("ex2.approx.f16x2 %0, %1;" : "=r"(d) : "r"(t));
    return d;
}
__device__ __forceinline__ uint32_t h2tanh(uint32_t t) {
    uint32_t d;
    asm("tanh.approx.f16x2 %0, %1;" : "=r"(d) : "r"(t));
    return d;
}

__device__ __forceinline__ void mma_f16(float* d, const uint32_t* a, const uint32_t* b) {
    asm volatile(
        "mma.sync.aligned.m16n8k16.row.col.f32.f16.f16.f32 "
        "{%0,%1,%2,%3}, {%4,%5,%6,%7}, {%8,%9}, {%0,%1,%2,%3};"
        : "+f"(d[0]), "+f"(d[1]), "+f"(d[2]), "+f"(d[3])
        : "r"(a[0]), "r"(a[1]), "r"(a[2]), "r"(a[3]), "r"(b[0]), "r"(b[1]));
}

__device__ __forceinline__ void ldsm_x4(uint32_t* r, uint32_t addr) {
    asm volatile("ldmatrix.sync.aligned.m8n8.x4.shared.b16 {%0,%1,%2,%3}, [%4];"
                 : "=r"(r[0]), "=r"(r[1]), "=r"(r[2]), "=r"(r[3]) : "r"(addr));
}
__device__ __forceinline__ void ldsm_x4_t(uint32_t* r, uint32_t addr) {
    asm volatile("ldmatrix.sync.aligned.m8n8.x4.trans.shared.b16 {%0,%1,%2,%3}, [%4];"
                 : "=r"(r[0]), "=r"(r[1]), "=r"(r[2]), "=r"(r[3]) : "r"(addr));
}

#define CP_ASYNC16(dst, src) \
    asm volatile("cp.async.ca.shared.global [%0], [%1], 16;" :: "r"(dst), "l"(src))
#define CP_COMMIT() asm volatile("cp.async.commit_group;" ::: "memory")
#define CP_WAIT0()  asm volatile("cp.async.wait_group 0;" ::: "memory")
#define CP_WAIT1()  asm volatile("cp.async.wait_group 1;" ::: "memory")

// ---------------- weight fold ----------------
__global__ __launch_bounds__(256)
void fold_w_kernel(const float* __restrict__ W, const float* __restrict__ gamma,
                   const float* __restrict__ beta, const float* __restrict__ b,
                   __half* __restrict__ Wo, float* __restrict__ bo, int N, int K) {
    int n = blockIdx.x * 8 + (threadIdx.x >> 5);
    if (n >= N) return;
    int lane = threadIdx.x & 31;
    const float* wr = W + (size_t)n * K;
    __half* wor = Wo + (size_t)n * K;
    float acc = 0.f;
    for (int k = lane; k < K; k += 32) {
        float w = wr[k];
        if (beta) acc += beta[k] * w;
        wor[k] = __float2half(gamma ? w * gamma[k] : w);
    }
    if (beta) {
        #pragma unroll
        for (int o = 16; o; o >>= 1) acc += __shfl_xor_sync(0xffffffffu, acc, o);
        if (lane == 0) bo[n] = b[n] + acc;
    }
}

// ---------------- conv weight transpose ----------------
__global__ __launch_bounds__(256)
void convT_kernel(const float* __restrict__ W, float* __restrict__ Wt, int C) {
    int idx = blockIdx.x * 256 + threadIdx.x;
    if (idx >= C * 64) return;
    int c = idx >> 6, k = idx & 63;
    Wt[k * C + c] = W[idx];
}

// ---------------- raw concat(x,f) -> half ----------------
__global__ __launch_bounds__(256)
void prep_xf_kernel(const float* __restrict__ x, const float* __restrict__ f,
                    __half* __restrict__ xf) {
    size_t idx = ((size_t)blockIdx.x * 256 + threadIdx.x) * 8;
    int r = (int)(idx / INCC);
    int c = (int)(idx % INCC);
    const float* src = (c < 512) ? (x + (size_t)r * 512 + c)
                                 : (f + (size_t)r * 128 + (c - 512));
    float4 a = *(const float4*)src;
    float4 b = *(const float4*)(src + 4);
    uint4 o;
    o.x = h2b(a.x, a.y); o.y = h2b(a.z, a.w);
    o.z = h2b(b.x, b.y); o.w = h2b(b.z, b.w);
    *(uint4*)(xf + idx) = o;
}

// ---------------- fused LN (fp32 input) ----------------
template<int K>
__global__ __launch_bounds__(256)
void ln_norm_kernel(const float* __restrict__ X, __half* __restrict__ Xn) {
    const int NSEG = K / 128;
    int row = blockIdx.x * 8 + (threadIdx.x >> 5);
    int lane = threadIdx.x & 31;
    const float* xr = X + (size_t)row * K;
    float4 v[NSEG];
    float s = 0.f, ss = 0.f;
    #pragma unroll
    for (int i = 0; i < NSEG; i++) {
        v[i] = *(const float4*)(xr + lane * 4 + i * 128);
        s  += v[i].x + v[i].y + v[i].z + v[i].w;
        ss += v[i].x * v[i].x + v[i].y * v[i].y + v[i].z * v[i].z + v[i].w * v[i].w;
    }
    #pragma unroll
    for (int o = 16; o; o >>= 1) {
        s  += __shfl_xor_sync(0xffffffffu, s, o);
        ss += __shfl_xor_sync(0xffffffffu, ss, o);
    }
    float mean = s / K;
    float rstd = rsqrtf(ss / K - mean * mean + 1e-5f);
    __half* xo = Xn + (size_t)row * K;
    #pragma unroll
    for (int i = 0; i < NSEG; i++) {
        uint2 o;
        o.x = h2b((v[i].x - mean) * rstd, (v[i].y - mean) * rstd);
        o.y = h2b((v[i].z - mean) * rstd, (v[i].w - mean) * rstd);
        *(uint2*)(xo + lane * 4 + i * 128) = o;
    }
}

// ---------------- fused LN (half input) ----------------
template<int K>
__global__ __launch_bounds__(256)
void ln_norm_h_kernel(const __half* __restrict__ X, __half* __restrict__ Xn, int row0) {
    const int NSEG = K / 128;
    int row = row0 + blockIdx.x * 8 + (threadIdx.x >> 5);
    int lane = threadIdx.x & 31;
    const __half* xr = X + (size_t)row * K;
    float v[NSEG][4];
    float s = 0.f, ss = 0.f;
    #pragma unroll
    for (int i = 0; i < NSEG; i++) {
        uint2 p = *(const uint2*)(xr + lane * 4 + i * 128);
        __half2 h0 = *(__half2*)&p.x;
        __half2 h1 = *(__half2*)&p.y;
        v[i][0] = __half2float(h0.x); v[i][1] = __half2float(h0.y);
        v[i][2] = __half2float(h1.x); v[i][3] = __half2float(h1.y);
        #pragma unroll
        for (int j = 0; j < 4; j++) { s += v[i][j]; ss += v[i][j] * v[i][j]; }
    }
    #pragma unroll
    for (int o = 16; o; o >>= 1) {
        s  += __shfl_xor_sync(0xffffffffu, s, o);
        ss += __shfl_xor_sync(0xffffffffu, ss, o);
    }
    float mean = s / K;
    float rstd = rsqrtf(ss / K - mean * mean + 1e-5f);
    __half* xo = Xn + (size_t)row * K;
    #pragma unroll
    for (int i = 0; i < NSEG; i++) {
        uint2 o;
        o.x = h2b((v[i][0] - mean) * rstd, (v[i][1] - mean) * rstd);
        o.y = h2b((v[i][2] - mean) * rstd, (v[i][3] - mean) * rstd);
        *(uint2*)(xo + lane * 4 + i * 128) = o;
    }
}

// ---------------- depthwise conv ----------------
template<int C, typename T>
__global__ __launch_bounds__(128)
void dwconv_kernel(const T* __restrict__ X, const float* __restrict__ Wt,
                   const float* __restrict__ bc, float* __restrict__ out) {
    int bw = blockIdx.y;
    int c = blockIdx.x * 128 + threadIdx.x;
    int b = bw >> 6;
    int g = bw & 63;
    int gh = g >> 3, gw = g & 7;
    const T* xb = X + ((size_t)b * NPIX + (size_t)(gh * 8) * 64 + gw * 8) * C + c;
    float s = bc[c];
    #pragma unroll
    for (int i = 0; i < 8; i++)
        #pragma unroll
        for (int j = 0; j < 8; j++)
            s += (float)xb[(size_t)(i * 64 + j) * C] * Wt[(i * 8 + j) * C + c];
    out[(size_t)bw * C + c] = s;
}

// ---------------- fp16 mma GEMM, 3-stage cp.async pipeline ----------------
#define GS 72
template<int MODE, int SPLIT>
__global__ __launch_bounds__(256)
void mma_gemm(const __half* __restrict__ A, const __half* __restrict__ W,
              const float* __restrict__ bias,
              float* __restrict__ Cf, __half* __restrict__ Ch, __half* __restrict__ Ch2,
              int M, int N, int K, int ldc, int m_off) {
    extern __shared__ __half sh[];
    __half* As = sh;                    // [3][128*GS]
    __half* Bs = sh + 3 * 128 * GS;     // [3][128*GS]

    const int tid = threadIdx.x;
    const int m0 = blockIdx.y * 128 + m_off;
    const int n0 = blockIdx.x * 128;
    const int q = tid & 7;
    const int lrow = tid >> 3;
    const int lane = tid & 31, grp = lane >> 2, tig = lane & 3;
    const int w = tid >> 5, mblk = (w & 3) * 32, nblk = (w >> 2) * 64;
    const int NC = K >> 6;

    const uint32_t as_s = (uint32_t)__cvta_generic_to_shared(As);
    const uint32_t bs_s = (uint32_t)__cvta_generic_to_shared(Bs);

    const uint32_t aoff0 = (uint32_t)(((mblk + (lane & 15)) * GS + (lane >> 4) * 8) * 2);
    const uint32_t aoff1 = aoff0 + (uint32_t)(16 * GS * 2);
    const uint32_t boff  = (uint32_t)(((nblk + (lane & 7) + ((lane & 16) ? 8 : 0)) * GS
                                       + ((lane & 8) ? 8 : 0)) * 2);

    int arow[4];
    #pragma unroll
    for (int i = 0; i < 4; i++) {
        int r = m0 + lrow + i * 32;
        arow[i] = (MODE == 3) ? win_map(r) : r;
    }

    float acc[2][8][4];
    #pragma unroll
    for (int mt = 0; mt < 2; mt++)
        #pragma unroll
        for (int nt = 0; nt < 8; nt++)
            #pragma unroll
            for (int e = 0; e < 4; e++) acc[mt][nt][e] = 0.f;

    auto issue = [&](int ch, int buf) {
        int gk = (ch << 6) + q * 8;
        #pragma unroll
        for (int i = 0; i < 4; i++) {
            int r = lrow + i * 32;
            CP_ASYNC16(as_s + (uint32_t)(((buf * 128 + r) * GS + q * 8) * 2),
                       A + (size_t)arow[i] * K + gk);
            CP_ASYNC16(bs_s + (uint32_t)(((buf * 128 + r) * GS + q * 8) * 2),
                       W + (size_t)(n0 + r) * K + gk);
        }
        CP_COMMIT();
    };
    auto compute = [&](int buf) {
        uint32_t abase = as_s + (uint32_t)(buf * 128 * GS * 2);
        uint32_t bbase = bs_s + (uint32_t)(buf * 128 * GS * 2);
        #pragma unroll
        for (int k16 = 0; k16 < 4; k16++) {
            uint32_t kb = (uint32_t)(k16 * 32);
            uint32_t af0[4], af1[4];
            ldsm_x4(af0, abase + aoff0 + kb);
            ldsm_x4(af1, abase + aoff1 + kb);
            #pragma unroll
            for (int p = 0; p < 4; p++) {
                uint32_t bf[4];
                ldsm_x4(bf, bbase + boff + (uint32_t)(p * 16 * GS * 2) + kb);
                mma_f16(acc[0][2 * p],     af0, bf);
                mma_f16(acc[1][2 * p],     af1, bf);
                mma_f16(acc[0][2 * p + 1], af0, bf + 2);
                mma_f16(acc[1][2 * p + 1], af1, bf + 2);
            }
        }
    };

    // 3-stage prologue: chunks 0 and 1 in flight
    issue(0, 0);
    issue(1, 1);
    CP_WAIT1();           // chunk 0 complete
    __syncthreads();

    int b0 = 0, b2 = 2;   // buffer of current chunk / of chunk+2
    for (int ch = 0; ch < NC; ch++) {
        int nx2 = ch + 2;
        if (nx2 < NC) issue(nx2, b2);
        compute(b0);
        if (nx2 < NC) CP_WAIT1();   // chunk ch+1 complete (ch+2 may be pending)
        else          CP_WAIT0();   // drain tail
        __syncthreads();
        b0 = (b0 == 2) ? 0 : b0 + 1;
        b2 = (b2 == 2) ? 0 : b2 + 1;
    }

    const __half2 hhalf = __floats2half2_rn(0.5f, 0.5f);
    #pragma unroll
    for (int mt = 0; mt < 2; mt++) {
        #pragma unroll
        for (int hr = 0; hr < 2; hr++) {
            int r = m0 + mblk + mt * 16 + grp + hr * 8;
            size_t orow = (MODE == 1) ? (size_t)win_map(r) : (size_t)r;
            #pragma unroll
            for (int nt = 0; nt < 8; nt++) {
                int c = n0 + nblk + nt * 8 + 2 * tig;
                float y0 = acc[mt][nt][hr * 2 + 0] + bias[c];
                float y1 = acc[mt][nt][hr * 2 + 1] + bias[c + 1];
                if (MODE == 0) {
                    __half2 a01 = *(const __half2*)(A + (size_t)r * K + c);
                    uint32_t th = h2tanh(h2b(y0 * 0.5f, y1 * 0.5f));
                    __half2 sig = __hfma2(*(__half2*)&th, hhalf, hhalf);
                    *(__half2*)(Ch + orow * (size_t)ldc + c) = __hmul2(a01, sig);
                } else if (MODE == 3) {
                    *(float2*)(Cf + orow * (size_t)ldc + c) = make_float2(y0, y1);
                } else {
                    __half* base = Ch;
                    int cc = c;
                    if (SPLIT) { base = (c < 512) ? Ch : Ch2; cc = c & 511; }
                    *(__half2*)(base + orow * (size_t)ldc + cc) = __floats2half2_rn(y0, y1);
                }
            }
        }
    }
}

// ---------------- attention: register softmax (ex2.f16x2) + trans-ldmatrix PV ----------------
#define AQ_STR 72
#define PS_STR 136
#define ATTN_SMEM_BYTES ((64*AQ_STR + 128*AQ_STR + 128*AQ_STR + 64*PS_STR) * 2 + 2 * 128 * 4)
#define C_LG2E 0.18033688f

__global__ __launch_bounds__(256)
void attn_kernel(const __half* __restrict__ Q, const __half* __restrict__ Kl,
                 const __half* __restrict__ Kg, const __half* __restrict__ Vl,
                 const __half* __restrict__ Vg, __half* __restrict__ O, int bid_off) {
    extern __shared__ char smraw[];
    __half* Qs = (__half*)smraw;
    __half* Ks = Qs + 64 * AQ_STR;
    __half* Vs = Ks + 128 * AQ_STR;
    __half* Ps = Vs + 128 * AQ_STR;
    float* Rmax = (float*)(Ps + 64 * PS_STR);
    float* Rsum = Rmax + 128;

    int bid = blockIdx.x + bid_off;
    int b = bid >> 9;
    int rem = bid & 511;
    int g = rem >> 3;
    int h = rem & 7;

    size_t wbase = ((size_t)(b * GG + g) * NWIN) * DD + (size_t)h * DHH;
    size_t gbase = ((size_t)b * NGLOB) * DD + (size_t)h * DHH;
    const __half* Qp  = Q  + wbase;
    const __half* Klp = Kl + wbase;
    const __half* Vlp = Vl + wbase;
    const __half* Kgp = Kg + gbase;
    const __half* Vgp = Vg + gbase;
    __half* Op = O + wbase;

    int tid = threadIdx.x;
    const uint32_t qs_s = (uint32_t)__cvta_generic_to_shared(Qs);
    const uint32_t ks_s = (uint32_t)__cvta_generic_to_shared(Ks);
    const uint32_t vs_s = (uint32_t)__cvta_generic_to_shared(Vs);
    const uint32_t ps_s = (uint32_t)__cvta_generic_to_shared(Ps);

    for (int e = tid; e < 64 * 8; e += 256) {
        int m = e >> 3, sg = e & 7;
        CP_ASYNC16(qs_s + (uint32_t)((m * AQ_STR + sg * 8) * 2), Qp + (size_t)m * DD + sg * 8);
    }
    for (int e = tid; e < 128 * 8; e += 256) {
        int kk = e >> 3, sg = e & 7;
        const __half* ksrc = (kk < 64) ? (Klp + (size_t)kk * DD)
                                       : (Kgp + (size_t)(kk - 64) * DD);
        CP_ASYNC16(ks_s + (uint32_t)((kk * AQ_STR + sg * 8) * 2), ksrc + sg * 8);
        const __half* vsrc = (kk < 64) ? (Vlp + (size_t)kk * DD)
                                       : (Vgp + (size_t)(kk - 64) * DD);
        CP_ASYNC16(vs_s + (uint32_t)((kk * AQ_STR + sg * 8) * 2), vsrc + sg * 8);
    }
    CP_COMMIT();
    CP_WAIT0();
    __syncthreads();

    int w = tid >> 5, lane = tid & 31, grp = lane >> 2, tig = lane & 3;
    int mrow = (w & 3) * 16;
    int hh = w >> 2;
    int nb0 = hh * 64;
    int r0 = mrow + grp, r1 = r0 + 8;

    float acc[8][4];
    {
        const uint32_t aoff = qs_s +
            (uint32_t)(((mrow + (lane & 15)) * AQ_STR + (lane >> 4) * 8) * 2);
        const uint32_t boff = ks_s +
            (uint32_t)(((nb0 + (lane & 7) + ((lane & 16) ? 8 : 0)) * AQ_STR
                        + ((lane & 8) ? 8 : 0)) * 2);
        #pragma unroll
        for (int nt = 0; nt < 8; nt++)
            #pragma unroll
            for (int e = 0; e < 4; e++) acc[nt][e] = 0.f;
        #pragma unroll
        for (int k16 = 0; k16 < 4; k16++) {
            uint32_t kb = (uint32_t)(k16 * 32);
            uint32_t af[4];
            ldsm_x4(af, aoff + kb);
            #pragma unroll
            for (int p = 0; p < 4; p++) {
                uint32_t bf[4];
                ldsm_x4(bf, boff + (uint32_t)(p * 16 * AQ_STR * 2) + kb);
                mma_f16(acc[2 * p],     af, bf);
                mma_f16(acc[2 * p + 1], af, bf + 2);
            }
        }
    }

    float m0 = -1e30f, m1 = -1e30f;
    #pragma unroll
    for (int nt = 0; nt < 8; nt++) {
        m0 = fmaxf(m0, fmaxf(acc[nt][0], acc[nt][1]));
        m1 = fmaxf(m1, fmaxf(acc[nt][2], acc[nt][3]));
    }
    m0 = fmaxf(m0, __shfl_xor_sync(0xffffffffu, m0, 1));
    m0 = fmaxf(m0, __shfl_xor_sync(0xffffffffu, m0, 2));
    m1 = fmaxf(m1, __shfl_xor_sync(0xffffffffu, m1, 1));
    m1 = fmaxf(m1, __shfl_xor_sync(0xffffffffu, m1, 2));
    if (tig == 0) {
        Rmax[hh * 64 + r0] = m0;
        Rmax[hh * 64 + r1] = m1;
    }
    __syncthreads();
    float M0 = fmaxf(Rmax[r0], Rmax[64 + r0]) * C_LG2E;
    float M1 = fmaxf(Rmax[r1], Rmax[64 + r1]) * C_LG2E;

    float s0 = 0.f, s1 = 0.f;
    #pragma unroll
    for (int nt = 0; nt < 8; nt++) {
        uint32_t p01 = h2ex2(h2b(acc[nt][0] * C_LG2E - M0, acc[nt][1] * C_LG2E - M0));
        uint32_t p23 = h2ex2(h2b(acc[nt][2] * C_LG2E - M1, acc[nt][3] * C_LG2E - M1));
        int c = nb0 + nt * 8 + 2 * tig;
        *(uint32_t*)&Ps[r0 * PS_STR + c] = p01;
        *(uint32_t*)&Ps[r1 * PS_STR + c] = p23;
        float2 f01 = __half22float2(*(__half2*)&p01);
        float2 f23 = __half22float2(*(__half2*)&p23);
        s0 += f01.x + f01.y;
        s1 += f23.x + f23.y;
    }
    s0 += __shfl_xor_sync(0xffffffffu, s0, 1);
    s0 += __shfl_xor_sync(0xffffffffu, s0, 2);
    s1 += __shfl_xor_sync(0xffffffffu, s1, 1);
    s1 += __shfl_xor_sync(0xffffffffu, s1, 2);
    if (tig == 0) {
        Rsum[hh * 64 + r0] = s0;
        Rsum[hh * 64 + r1] = s1;
    }
    __syncthreads();
    float inv0 = 1.f / (Rsum[r0] + Rsum[64 + r0]);
    float inv1 = 1.f / (Rsum[r1] + Rsum[64 + r1]);

    {
        int db0 = hh * 32;
        const uint32_t aoff = ps_s +
            (uint32_t)(((mrow + (lane & 15)) * PS_STR + (lane >> 4) * 8) * 2);
        const uint32_t bvoff = vs_s +
            (uint32_t)((((lane & 7) + ((lane & 8) ? 8 : 0)) * AQ_STR
                        + db0 + ((lane & 16) ? 8 : 0)) * 2);
        float pac[4][4];
        #pragma unroll
        for (int nt = 0; nt < 4; nt++)
            #pragma unroll
            for (int e = 0; e < 4; e++) pac[nt][e] = 0.f;
        #pragma unroll
        for (int k16 = 0; k16 < 8; k16++) {
            uint32_t kba = (uint32_t)(k16 * 32);
            uint32_t kbb = (uint32_t)(k16 * 16 * AQ_STR * 2);
            uint32_t af[4];
            ldsm_x4(af, aoff + kba);
            #pragma unroll
            for (int p = 0; p < 2; p++) {
                uint32_t bf[4];
                ldsm_x4_t(bf, bvoff + (uint32_t)(p * 16 * 2) + kbb);
                mma_f16(pac[2 * p],     af, bf);
                mma_f16(pac[2 * p + 1], af, bf + 2);
            }
        }
        #pragma unroll
        for (int nt = 0; nt < 4; nt++) {
            int c = db0 + nt * 8 + 2 * tig;
            *(__half2*)(Op + (size_t)r0 * DD + c) =
                __floats2half2_rn(pac[nt][0] * inv0, pac[nt][1] * inv0);
            *(__half2*)(Op + (size_t)r1 * DD + c) =
                __floats2half2_rn(pac[nt][2] * inv1, pac[nt][3] * inv1);
        }
    }
}

// ---------------- launch ----------------
#define SMEM_GEMM (6 * 128 * GS * 2)   // 110592 (3-stage)
#define MH (MTOK / 2)

extern "C" void kernel_launch(void* const* d_in, const int* in_sizes, int n_in,
                              void* d_out, int out_size) {
    const float* x       = (const float*)d_in[0];
    const float* f       = (const float*)d_in[1];
    const float* wq      = (const float*)d_in[2];
    const float* bq      = (const float*)d_in[3];
    const float* wk      = (const float*)d_in[4];
    const float* bk      = (const float*)d_in[5];
    const float* wv      = (const float*)d_in[6];
    const float* bv      = (const float*)d_in[7];
    const float* wo      = (const float*)d_in[8];
    const float* bo      = (const float*)d_in[9];
    const float* rw_w    = (const float*)d_in[10];
    const float* rw_b    = (const float*)d_in[11];
    const float* convk_w = (const float*)d_in[12];
    const float* convk_b = (const float*)d_in[13];
    const float* convv_w = (const float*)d_in[14];
    const float* convv_b = (const float*)d_in[15];
    const float* qn_g    = (const float*)d_in[16];
    const float* qn_b    = (const float*)d_in[17];
    const float* kn_g    = (const float*)d_in[18];
    const float* kn_b    = (const float*)d_in[19];
    const float* vn_g    = (const float*)d_in[20];
    const float* vn_b    = (const float*)d_in[21];
    float* out = (float*)d_out;

    float *kg, *vg, *fbqk, *fbv, *cvT, *ckT;
    __half *xf, *qkh, *qkn, *xn, *kgn, *vgn, *Q, *Kl, *Vl, *Kg, *Vg, *O;
    __half *fwqk, *fwv, *fwo, *frw;
    cudaGetSymbolAddress((void**)&kg,   g_kg);
    cudaGetSymbolAddress((void**)&vg,   g_vg);
    cudaGetSymbolAddress((void**)&xf,   g_xf);
    cudaGetSymbolAddress((void**)&qkh,  g_qkh);
    cudaGetSymbolAddress((void**)&qkn,  g_qkn);
    cudaGetSymbolAddress((void**)&xn,   g_xn);
    cudaGetSymbolAddress((void**)&kgn,  g_kgn);
    cudaGetSymbolAddress((void**)&vgn,  g_vgn);
    cudaGetSymbolAddress((void**)&Q,    g_Q);
    cudaGetSymbolAddress((void**)&Kl,   g_Kl);
    cudaGetSymbolAddress((void**)&Vl,   g_Vl);
    cudaGetSymbolAddress((void**)&Kg,   g_Kg);
    cudaGetSymbolAddress((void**)&Vg,   g_Vg);
    cudaGetSymbolAddress((void**)&O,    g_O);
    cudaGetSymbolAddress((void**)&fwqk, g_fwqk);
    cudaGetSymbolAddress((void**)&fbqk, g_fbqk);
    cudaGetSymbolAddress((void**)&fwv,  g_fwv);
    cudaGetSymbolAddress((void**)&fwo,  g_fwo);
    cudaGetSymbolAddress((void**)&frw,  g_frw);
    cudaGetSymbolAddress((void**)&fbv,  g_fbv);
    cudaGetSymbolAddress((void**)&cvT,  g_cvT);
    cudaGetSymbolAddress((void**)&ckT,  g_ckT);

    cudaFuncSetAttribute(attn_kernel, cudaFuncAttributeMaxDynamicSharedMemorySize,
                         ATTN_SMEM_BYTES);
    cudaFuncSetAttribute(mma_gemm<0,0>, cudaFuncAttributeMaxDynamicSharedMemorySize, SMEM_GEMM);
    cudaFuncSetAttribute(mma_gemm<1,1>, cudaFuncAttributeMaxDynamicSharedMemorySize, SMEM_GEMM);
    cudaFuncSetAttribute(mma_gemm<1,0>, cudaFuncAttributeMaxDynamicSharedMemorySize, SMEM_GEMM);
    cudaFuncSetAttribute(mma_gemm<2,0>, cudaFuncAttributeMaxDynamicSharedMemorySize, SMEM_GEMM);
    cudaFuncSetAttribute(mma_gemm<3,0>, cudaFuncAttributeMaxDynamicSharedMemorySize, SMEM_GEMM);

    cudaStream_t s1, s2;
    cudaStreamCreateWithFlags(&s1, cudaStreamNonBlocking);
    cudaStreamCreateWithFlags(&s2, cudaStreamNonBlocking);
    cudaEvent_t evFork, evFRW, evJoinV, evPrep, evRW0, evRW1, evQK1, evJoinKG, evA0, evO0;
    cudaEventCreateWithFlags(&evFork,   cudaEventDisableTiming);
    cudaEventCreateWithFlags(&evFRW,    cudaEventDisableTiming);
    cudaEventCreateWithFlags(&evJoinV,  cudaEventDisableTiming);
    cudaEventCreateWithFlags(&evPrep,   cudaEventDisableTiming);
    cudaEventCreateWithFlags(&evRW0,    cudaEventDisableTiming);
    cudaEventCreateWithFlags(&evRW1,    cudaEventDisableTiming);
    cudaEventCreateWithFlags(&evQK1,    cudaEventDisableTiming);
    cudaEventCreateWithFlags(&evJoinKG, cudaEventDisableTiming);
    cudaEventCreateWithFlags(&evA0,     cudaEventDisableTiming);
    cudaEventCreateWithFlags(&evO0,     cudaEventDisableTiming);

    cudaEventRecord(evFork, 0);
    cudaStreamWaitEvent(s1, evFork, 0);
    cudaStreamWaitEvent(s2, evFork, 0);

    // ---- s1: frw fold first, then x-side chain ----
    fold_w_kernel<<<80, 256, 0, s1>>>(rw_w, nullptr, nullptr, nullptr, frw, nullptr, INCC, INCC);
    cudaEventRecord(evFRW, s1);
    fold_w_kernel<<<64, 256, 0, s1>>>(wv, vn_g, vn_b, bv, fwv, fbv, DD, DD);
    fold_w_kernel<<<64, 256, 0, s1>>>(wo, nullptr, nullptr, nullptr, fwo, nullptr, DD, DD);
    fold_w_kernel<<<64, 256, 0, s1>>>(wq, qn_g, qn_b, bq, fwqk, fbqk, DD, INCC);
    fold_w_kernel<<<64, 256, 0, s1>>>(wk, kn_g, kn_b, bk, fwqk + (size_t)DD * INCC, fbqk + DD, DD, INCC);
    convT_kernel<<<(DD * 64) / 256, 256, 0, s1>>>(convv_w, cvT, DD);
    convT_kernel<<<(INCC * 64) / 256, 256, 0, s1>>>(convk_w, ckT, INCC);
    ln_norm_kernel<512><<<MTOK / 8, 256, 0, s1>>>(x, xn);
    dwconv_kernel<512,float><<<dim3(4, BT * GG), 128, 0, s1>>>(x, cvT, convv_b, vg);
    ln_norm_kernel<512><<<(BT * NGLOB) / 8, 256, 0, s1>>>(vg, vgn);
    mma_gemm<1,0><<<dim3(4, 256), 256, SMEM_GEMM, s1>>>(
        xn, fwv, fbv, nullptr, Vl, nullptr, MTOK, DD, DD, DD, 0);
    mma_gemm<2,0><<<dim3(4, 4), 256, SMEM_GEMM, s1>>>(
        vgn, fwv, fbv, nullptr, Vg, nullptr, BT * NGLOB, DD, DD, DD, 0);
    cudaEventRecord(evJoinV, s1);

    // ---- default stream: prep then rw half0 chain ----
    prep_xf_kernel<<<MTOK * INCC / 2048, 256>>>(x, f, xf);
    cudaEventRecord(evPrep, 0);

    cudaStreamWaitEvent(0, evFRW, 0);
    mma_gemm<0,0><<<dim3(5, 128), 256, SMEM_GEMM>>>(
        xf, frw, rw_b, nullptr, qkh, nullptr, MTOK, INCC, INCC, INCC, 0);
    cudaEventRecord(evRW0, 0);
    ln_norm_h_kernel<640><<<MH / 8, 256>>>(qkh, qkn, 0);
    mma_gemm<1,1><<<dim3(8, 128), 256, SMEM_GEMM>>>(
        qkn, fwqk, fbqk, nullptr, Q, Kl, MTOK, 2 * DD, INCC, DD, 0);

    // ---- s2: rw half1 chain ----
    cudaStreamWaitEvent(s2, evPrep, 0);
    cudaStreamWaitEvent(s2, evFRW, 0);
    mma_gemm<0,0><<<dim3(5, 128), 256, SMEM_GEMM, s2>>>(
        xf, frw, rw_b, nullptr, qkh, nullptr, MTOK, INCC, INCC, INCC, MH);
    cudaEventRecord(evRW1, s2);
    ln_norm_h_kernel<640><<<MH / 8, 256, 0, s2>>>(qkh, qkn, MH);
    mma_gemm<1,1><<<dim3(8, 128), 256, SMEM_GEMM, s2>>>(
        qkn, fwqk, fbqk, nullptr, Q, Kl, MTOK, 2 * DD, INCC, DD, MH);
    cudaEventRecord(evQK1, s2);

    // ---- s1: kg chain ----
    cudaStreamWaitEvent(s1, evRW0, 0);
    cudaStreamWaitEvent(s1, evRW1, 0);
    dwconv_kernel<640,__half><<<dim3(5, BT * GG), 128, 0, s1>>>(qkh, ckT, convk_b, kg);
    ln_norm_kernel<640><<<(BT * NGLOB) / 8, 256, 0, s1>>>(kg, kgn);
    mma_gemm<2,0><<<dim3(4, 4), 256, SMEM_GEMM, s1>>>(
        kgn, fwqk + (size_t)DD * INCC, fbqk + DD, nullptr, Kg, nullptr,
        BT * NGLOB, DD, INCC, DD, 0);
    cudaEventRecord(evJoinKG, s1);

    // ---- tail: staggered attention + out-projection ----
    cudaStreamWaitEvent(0, evJoinV, 0);
    cudaStreamWaitEvent(0, evJoinKG, 0);
    attn_kernel<<<BT * GG * NHEAD / 2, 256, ATTN_SMEM_BYTES>>>(Q, Kl, Kg, Vl, Vg, O, 0);
    cudaEventRecord(evA0, 0);
    cudaStreamWaitEvent(0, evQK1, 0);
    attn_kernel<<<BT * GG * NHEAD / 2, 256, ATTN_SMEM_BYTES>>>(Q, Kl, Kg, Vl, Vg, O,
                                                               BT * GG * NHEAD / 2);
    cudaStreamWaitEvent(s2, evA0, 0);
    cudaStreamWaitEvent(s2, evJoinV, 0);
    mma_gemm<3,0><<<dim3(4, 128), 256, SMEM_GEMM, s2>>>(
        O, fwo, bo, out, nullptr, nullptr, MTOK, DD, DD, DD, 0);
    cudaEventRecord(evO0, s2);
    mma_gemm<3,0><<<dim3(4, 128), 256, SMEM_GEMM>>>(
        O, fwo, bo, out, nullptr, nullptr, MTOK, DD, DD, DD, MH);
    cudaStreamWaitEvent(0, evO0, 0);

    cudaEventDestroy(evFork);
    cudaEventDestroy(evFRW);
    cudaEventDestroy(evJoinV);
    cudaEventDestroy(evPrep);
    cudaEventDestroy(evRW0);
    cudaEventDestroy(evRW1);
    cudaEventDestroy(evQK1);
    cudaEventDestroy(evJoinKG);
    cudaEventDestroy(evA0);
    cudaEventDestroy(evO0);
    cudaStreamDestroy(s1);
    cudaStreamDestroy(s2);
}

// round 16
// speedup vs baseline: 1.1252x; 1.1252x over previous
#include <cuda_runtime.h>
#include <cuda_fp16.h>
#include <cstdint>

// ---------------- problem constants ----------------
#define BT     8
#define NPIX   4096
#define DD     512
#define CFF    128
#define INCC   640
#define GG     64
#define NWIN   64
#define NGLOB  64
#define NHEAD  8
#define DHH    64
#define MTOK   32768

// ---------------- scratch ----------------
__device__ float  g_kg [BT*NGLOB*INCC];
__device__ float  g_vg [BT*NGLOB*DD];
__device__ __half g_xf [MTOK*INCC];
__device__ __half g_qkh[MTOK*INCC];
__device__ __half g_qkn[MTOK*INCC];
__device__ __half g_xn [MTOK*DD];
__device__ __half g_kgn[BT*NGLOB*INCC];
__device__ __half g_vgn[BT*NGLOB*DD];
__device__ __half g_Q  [MTOK*DD];
__device__ __half g_Kl [MTOK*DD];
__device__ __half g_Vl [MTOK*DD];
__device__ __half g_Kg [BT*NGLOB*DD];
__device__ __half g_Vg [BT*NGLOB*DD];
__device__ __half g_O  [MTOK*DD];
__device__ __half g_fwqk[2*DD*INCC];
__device__ float  g_fbqk[2*DD];
__device__ __half g_fwv[DD*DD];
__device__ __half g_fwo[DD*DD];
__device__ __half g_frw[INCC*INCC];
__device__ float  g_fbv[DD];
__device__ float  g_cvT[64*DD];
__device__ float  g_ckT[64*INCC];

// ---------------- helpers ----------------
__device__ __forceinline__ int win_map(int r) {
    int b = r >> 12;
    int p = r & 4095;
    int h = p >> 6, w = p & 63;
    int g = ((h >> 3) << 3) | (w >> 3);
    int n = ((h & 7) << 3) | (w & 7);
    return (((b << 6) | g) << 6) | n;
}

__device__ __forceinline__ uint32_t h2b(float a, float b) {
    __half2 h = __floats2half2_rn(a, b);
    return *(uint32_t*)&h;
}
__device__ __forceinline__ uint32_t h2ex2(uint32_t t) {
    uint32_t d;
    asm("ex2.approx.f16x2 %0, %1;" : "=r"(d) : "r"(t));
    return d;
}
__device__ __forceinline__ uint32_t h2tanh(uint32_t t) {
    uint32_t d;
    asm("tanh.approx.f16x2 %0, %1;" : "=r"(d) : "r"(t));
    return d;
}

__device__ __forceinline__ void mma_f16(float* d, const uint32_t* a, const uint32_t* b) {
    asm volatile(
        "mma.sync.aligned.m16n8k16.row.col.f32.f16.f16.f32 "
        "{%0,%1,%2,%3}, {%4,%5,%6,%7}, {%8,%9}, {%0,%1,%2,%3};"
        : "+f"(d[0]), "+f"(d[1]), "+f"(d[2]), "+f"(d[3])
        : "r"(a[0]), "r"(a[1]), "r"(a[2]), "r"(a[3]), "r"(b[0]), "r"(b[1]));
}

__device__ __forceinline__ void ldsm_x4(uint32_t* r, uint32_t addr) {
    asm volatile("ldmatrix.sync.aligned.m8n8.x4.shared.b16 {%0,%1,%2,%3}, [%4];"
                 : "=r"(r[0]), "=r"(r[1]), "=r"(r[2]), "=r"(r[3]) : "r"(addr));
}
__device__ __forceinline__ void ldsm_x4_t(uint32_t* r, uint32_t addr) {
    asm volatile("ldmatrix.sync.aligned.m8n8.x4.trans.shared.b16 {%0,%1,%2,%3}, [%4];"
                 : "=r"(r[0]), "=r"(r[1]), "=r"(r[2]), "=r"(r[3]) : "r"(addr));
}

#define CP_ASYNC16(dst, src) \
    asm volatile("cp.async.ca.shared.global [%0], [%1], 16;" :: "r"(dst), "l"(src))
#define CP_COMMIT() asm volatile("cp.async.commit_group;" ::: "memory")
#define CP_WAIT0()  asm volatile("cp.async.wait_group 0;" ::: "memory")

// ---------------- weight fold ----------------
__global__ __launch_bounds__(256)
void fold_w_kernel(const float* __restrict__ W, const float* __restrict__ gamma,
                   const float* __restrict__ beta, const float* __restrict__ b,
                   __half* __restrict__ Wo, float* __restrict__ bo, int N, int K) {
    int n = blockIdx.x * 8 + (threadIdx.x >> 5);
    if (n >= N) return;
    int lane = threadIdx.x & 31;
    const float* wr = W + (size_t)n * K;
    __half* wor = Wo + (size_t)n * K;
    float acc = 0.f;
    for (int k = lane; k < K; k += 32) {
        float w = wr[k];
        if (beta) acc += beta[k] * w;
        wor[k] = __float2half(gamma ? w * gamma[k] : w);
    }
    if (beta) {
        #pragma unroll
        for (int o = 16; o; o >>= 1) acc += __shfl_xor_sync(0xffffffffu, acc, o);
        if (lane == 0) bo[n] = b[n] + acc;
    }
}

// ---------------- conv weight transpose ----------------
__global__ __launch_bounds__(256)
void convT_kernel(const float* __restrict__ W, float* __restrict__ Wt, int C) {
    int idx = blockIdx.x * 256 + threadIdx.x;
    if (idx >= C * 64) return;
    int c = idx >> 6, k = idx & 63;
    Wt[k * C + c] = W[idx];
}

// ---------------- raw concat(x,f) -> half ----------------
__global__ __launch_bounds__(256)
void prep_xf_kernel(const float* __restrict__ x, const float* __restrict__ f,
                    __half* __restrict__ xf) {
    size_t idx = ((size_t)blockIdx.x * 256 + threadIdx.x) * 8;
    int r = (int)(idx / INCC);
    int c = (int)(idx % INCC);
    const float* src = (c < 512) ? (x + (size_t)r * 512 + c)
                                 : (f + (size_t)r * 128 + (c - 512));
    float4 a = *(const float4*)src;
    float4 b = *(const float4*)(src + 4);
    uint4 o;
    o.x = h2b(a.x, a.y); o.y = h2b(a.z, a.w);
    o.z = h2b(b.x, b.y); o.w = h2b(b.z, b.w);
    *(uint4*)(xf + idx) = o;
}

// ---------------- fused LN (fp32 input) ----------------
template<int K>
__global__ __launch_bounds__(256)
void ln_norm_kernel(const float* __restrict__ X, __half* __restrict__ Xn) {
    const int NSEG = K / 128;
    int row = blockIdx.x * 8 + (threadIdx.x >> 5);
    int lane = threadIdx.x & 31;
    const float* xr = X + (size_t)row * K;
    float4 v[NSEG];
    float s = 0.f, ss = 0.f;
    #pragma unroll
    for (int i = 0; i < NSEG; i++) {
        v[i] = *(const float4*)(xr + lane * 4 + i * 128);
        s  += v[i].x + v[i].y + v[i].z + v[i].w;
        ss += v[i].x * v[i].x + v[i].y * v[i].y + v[i].z * v[i].z + v[i].w * v[i].w;
    }
    #pragma unroll
    for (int o = 16; o; o >>= 1) {
        s  += __shfl_xor_sync(0xffffffffu, s, o);
        ss += __shfl_xor_sync(0xffffffffu, ss, o);
    }
    float mean = s / K;
    float rstd = rsqrtf(ss / K - mean * mean + 1e-5f);
    __half* xo = Xn + (size_t)row * K;
    #pragma unroll
    for (int i = 0; i < NSEG; i++) {
        uint2 o;
        o.x = h2b((v[i].x - mean) * rstd, (v[i].y - mean) * rstd);
        o.y = h2b((v[i].z - mean) * rstd, (v[i].w - mean) * rstd);
        *(uint2*)(xo + lane * 4 + i * 128) = o;
    }
}

// ---------------- fused LN (half input) ----------------
template<int K>
__global__ __launch_bounds__(256)
void ln_norm_h_kernel(const __half* __restrict__ X, __half* __restrict__ Xn, int row0) {
    const int NSEG = K / 128;
    int row = row0 + blockIdx.x * 8 + (threadIdx.x >> 5);
    int lane = threadIdx.x & 31;
    const __half* xr = X + (size_t)row * K;
    float v[NSEG][4];
    float s = 0.f, ss = 0.f;
    #pragma unroll
    for (int i = 0; i < NSEG; i++) {
        uint2 p = *(const uint2*)(xr + lane * 4 + i * 128);
        __half2 h0 = *(__half2*)&p.x;
        __half2 h1 = *(__half2*)&p.y;
        v[i][0] = __half2float(h0.x); v[i][1] = __half2float(h0.y);
        v[i][2] = __half2float(h1.x); v[i][3] = __half2float(h1.y);
        #pragma unroll
        for (int j = 0; j < 4; j++) { s += v[i][j]; ss += v[i][j] * v[i][j]; }
    }
    #pragma unroll
    for (int o = 16; o; o >>= 1) {
        s  += __shfl_xor_sync(0xffffffffu, s, o);
        ss += __shfl_xor_sync(0xffffffffu, ss, o);
    }
    float mean = s / K;
    float rstd = rsqrtf(ss / K - mean * mean + 1e-5f);
    __half* xo = Xn + (size_t)row * K;
    #pragma unroll
    for (int i = 0; i < NSEG; i++) {
        uint2 o;
        o.x = h2b((v[i][0] - mean) * rstd, (v[i][1] - mean) * rstd);
        o.y = h2b((v[i][2] - mean) * rstd, (v[i][3] - mean) * rstd);
        *(uint2*)(xo + lane * 4 + i * 128) = o;
    }
}

// ---------------- depthwise conv ----------------
template<int C, typename T>
__global__ __launch_bounds__(128)
void dwconv_kernel(const T* __restrict__ X, const float* __restrict__ Wt,
                   const float* __restrict__ bc, float* __restrict__ out) {
    int bw = blockIdx.y;
    int c = blockIdx.x * 128 + threadIdx.x;
    int b = bw >> 6;
    int g = bw & 63;
    int gh = g >> 3, gw = g & 7;
    const T* xb = X + ((size_t)b * NPIX + (size_t)(gh * 8) * 64 + gw * 8) * C + c;
    float s = bc[c];
    #pragma unroll
    for (int i = 0; i < 8; i++)
        #pragma unroll
        for (int j = 0; j < 8; j++)
            s += (float)xb[(size_t)(i * 64 + j) * C] * Wt[(i * 8 + j) * C + c];
    out[(size_t)bw * C + c] = s;
}

// ---------------- fp16 mma GEMM, 2-stage cp.async (reverted) ----------------
#define GS 72
template<int MODE, int SPLIT>
__global__ __launch_bounds__(256)
void mma_gemm(const __half* __restrict__ A, const __half* __restrict__ W,
              const float* __restrict__ bias,
              float* __restrict__ Cf, __half* __restrict__ Ch, __half* __restrict__ Ch2,
              int M, int N, int K, int ldc, int m_off) {
    extern __shared__ __half sh[];
    __half* As = sh;
    __half* Bs = sh + 2 * 128 * GS;

    const int tid = threadIdx.x;
    const int m0 = blockIdx.y * 128 + m_off;
    const int n0 = blockIdx.x * 128;
    const int q = tid & 7;
    const int lrow = tid >> 3;
    const int lane = tid & 31, grp = lane >> 2, tig = lane & 3;
    const int w = tid >> 5, mblk = (w & 3) * 32, nblk = (w >> 2) * 64;
    const int NC = K >> 6;

    const uint32_t as_s = (uint32_t)__cvta_generic_to_shared(As);
    const uint32_t bs_s = (uint32_t)__cvta_generic_to_shared(Bs);

    const uint32_t aoff0 = (uint32_t)(((mblk + (lane & 15)) * GS + (lane >> 4) * 8) * 2);
    const uint32_t aoff1 = aoff0 + (uint32_t)(16 * GS * 2);
    const uint32_t boff  = (uint32_t)(((nblk + (lane & 7) + ((lane & 16) ? 8 : 0)) * GS
                                       + ((lane & 8) ? 8 : 0)) * 2);

    int arow[4];
    #pragma unroll
    for (int i = 0; i < 4; i++) {
        int r = m0 + lrow + i * 32;
        arow[i] = (MODE == 3) ? win_map(r) : r;
    }

    float acc[2][8][4];
    #pragma unroll
    for (int mt = 0; mt < 2; mt++)
        #pragma unroll
        for (int nt = 0; nt < 8; nt++)
            #pragma unroll
            for (int e = 0; e < 4; e++) acc[mt][nt][e] = 0.f;

    auto issue = [&](int ch, int buf) {
        int gk = (ch << 6) + q * 8;
        #pragma unroll
        for (int i = 0; i < 4; i++) {
            int r = lrow + i * 32;
            CP_ASYNC16(as_s + (uint32_t)(((buf * 128 + r) * GS + q * 8) * 2),
                       A + (size_t)arow[i] * K + gk);
            CP_ASYNC16(bs_s + (uint32_t)(((buf * 128 + r) * GS + q * 8) * 2),
                       W + (size_t)(n0 + r) * K + gk);
        }
        CP_COMMIT();
    };
    auto compute = [&](int buf) {
        uint32_t abase = as_s + (uint32_t)(buf * 128 * GS * 2);
        uint32_t bbase = bs_s + (uint32_t)(buf * 128 * GS * 2);
        #pragma unroll
        for (int k16 = 0; k16 < 4; k16++) {
            uint32_t kb = (uint32_t)(k16 * 32);
            uint32_t af0[4], af1[4];
            ldsm_x4(af0, abase + aoff0 + kb);
            ldsm_x4(af1, abase + aoff1 + kb);
            #pragma unroll
            for (int p = 0; p < 4; p++) {
                uint32_t bf[4];
                ldsm_x4(bf, bbase + boff + (uint32_t)(p * 16 * GS * 2) + kb);
                mma_f16(acc[0][2 * p],     af0, bf);
                mma_f16(acc[1][2 * p],     af1, bf);
                mma_f16(acc[0][2 * p + 1], af0, bf + 2);
                mma_f16(acc[1][2 * p + 1], af1, bf + 2);
            }
        }
    };

    issue(0, 0);
    CP_WAIT0();
    __syncthreads();

    for (int ch = 0; ch < NC; ch++) {
        int buf = ch & 1;
        int nx = ch + 1;
        if (nx < NC) issue(nx, buf ^ 1);
        compute(buf);
        if (nx < NC) CP_WAIT0();
        __syncthreads();
    }

    const __half2 hhalf = __floats2half2_rn(0.5f, 0.5f);
    #pragma unroll
    for (int mt = 0; mt < 2; mt++) {
        #pragma unroll
        for (int hr = 0; hr < 2; hr++) {
            int r = m0 + mblk + mt * 16 + grp + hr * 8;
            size_t orow = (MODE == 1) ? (size_t)win_map(r) : (size_t)r;
            #pragma unroll
            for (int nt = 0; nt < 8; nt++) {
                int c = n0 + nblk + nt * 8 + 2 * tig;
                float y0 = acc[mt][nt][hr * 2 + 0] + bias[c];
                float y1 = acc[mt][nt][hr * 2 + 1] + bias[c + 1];
                if (MODE == 0) {
                    __half2 a01 = *(const __half2*)(A + (size_t)r * K + c);
                    uint32_t th = h2tanh(h2b(y0 * 0.5f, y1 * 0.5f));
                    __half2 sig = __hfma2(*(__half2*)&th, hhalf, hhalf);
                    *(__half2*)(Ch + orow * (size_t)ldc + c) = __hmul2(a01, sig);
                } else if (MODE == 3) {
                    *(float2*)(Cf + orow * (size_t)ldc + c) = make_float2(y0, y1);
                } else {
                    __half* base = Ch;
                    int cc = c;
                    if (SPLIT) { base = (c < 512) ? Ch : Ch2; cc = c & 511; }
                    *(__half2*)(base + orow * (size_t)ldc + cc) = __floats2half2_rn(y0, y1);
                }
            }
        }
    }
}

// ---------------- attention: register softmax + register-fragment PV ----------------
#define AQ_STR 72
#define PP_STR 68
// Qs + Ks + Vs halves, Pp fp32 partials [4][16][68], Rmax/Rsum
#define ATTN_SMEM_BYTES ((64*AQ_STR + 128*AQ_STR + 128*AQ_STR) * 2 + 4*16*PP_STR*4 + 2*128*4)
#define C_LG2E 0.18033688f

__global__ __launch_bounds__(256)
void attn_kernel(const __half* __restrict__ Q, const __half* __restrict__ Kl,
                 const __half* __restrict__ Kg, const __half* __restrict__ Vl,
                 const __half* __restrict__ Vg, __half* __restrict__ O, int bid_off) {
    extern __shared__ char smraw[];
    __half* Qs = (__half*)smraw;
    __half* Ks = Qs + 64 * AQ_STR;
    __half* Vs = Ks + 128 * AQ_STR;
    float* Pp  = (float*)(Vs + 128 * AQ_STR);     // [4][16][PP_STR]
    float* Rmax = Pp + 4 * 16 * PP_STR;           // [2][64]
    float* Rsum = Rmax + 128;

    int bid = blockIdx.x + bid_off;
    int b = bid >> 9;
    int rem = bid & 511;
    int g = rem >> 3;
    int h = rem & 7;

    size_t wbase = ((size_t)(b * GG + g) * NWIN) * DD + (size_t)h * DHH;
    size_t gbase = ((size_t)b * NGLOB) * DD + (size_t)h * DHH;
    const __half* Qp  = Q  + wbase;
    const __half* Klp = Kl + wbase;
    const __half* Vlp = Vl + wbase;
    const __half* Kgp = Kg + gbase;
    const __half* Vgp = Vg + gbase;
    __half* Op = O + wbase;

    int tid = threadIdx.x;
    const uint32_t qs_s = (uint32_t)__cvta_generic_to_shared(Qs);
    const uint32_t ks_s = (uint32_t)__cvta_generic_to_shared(Ks);
    const uint32_t vs_s = (uint32_t)__cvta_generic_to_shared(Vs);

    for (int e = tid; e < 64 * 8; e += 256) {
        int m = e >> 3, sg = e & 7;
        CP_ASYNC16(qs_s + (uint32_t)((m * AQ_STR + sg * 8) * 2), Qp + (size_t)m * DD + sg * 8);
    }
    for (int e = tid; e < 128 * 8; e += 256) {
        int kk = e >> 3, sg = e & 7;
        const __half* ksrc = (kk < 64) ? (Klp + (size_t)kk * DD)
                                       : (Kgp + (size_t)(kk - 64) * DD);
        CP_ASYNC16(ks_s + (uint32_t)((kk * AQ_STR + sg * 8) * 2), ksrc + sg * 8);
        const __half* vsrc = (kk < 64) ? (Vlp + (size_t)kk * DD)
                                       : (Vgp + (size_t)(kk - 64) * DD);
        CP_ASYNC16(vs_s + (uint32_t)((kk * AQ_STR + sg * 8) * 2), vsrc + sg * 8);
    }
    CP_COMMIT();
    CP_WAIT0();
    __syncthreads();

    int w = tid >> 5, lane = tid & 31, grp = lane >> 2, tig = lane & 3;
    int mrow = (w & 3) * 16;
    int hh = w >> 2;
    int nb0 = hh * 64;
    int r0 = mrow + grp, r1 = r0 + 8;
    int pair = w & 3;

    // ---- QK: per warp m16 x n64, k64 ----
    float acc[8][4];
    {
        const uint32_t aoff = qs_s +
            (uint32_t)(((mrow + (lane & 15)) * AQ_STR + (lane >> 4) * 8) * 2);
        const uint32_t boff = ks_s +
            (uint32_t)(((nb0 + (lane & 7) + ((lane & 16) ? 8 : 0)) * AQ_STR
                        + ((lane & 8) ? 8 : 0)) * 2);
        #pragma unroll
        for (int nt = 0; nt < 8; nt++)
            #pragma unroll
            for (int e = 0; e < 4; e++) acc[nt][e] = 0.f;
        #pragma unroll
        for (int k16 = 0; k16 < 4; k16++) {
            uint32_t kb = (uint32_t)(k16 * 32);
            uint32_t af[4];
            ldsm_x4(af, aoff + kb);
            #pragma unroll
            for (int p = 0; p < 4; p++) {
                uint32_t bf[4];
                ldsm_x4(bf, boff + (uint32_t)(p * 16 * AQ_STR * 2) + kb);
                mma_f16(acc[2 * p],     af, bf);
                mma_f16(acc[2 * p + 1], af, bf + 2);
            }
        }
    }

    // ---- softmax stats; keep exp as packed half2 register fragments ----
    float m0 = -1e30f, m1 = -1e30f;
    #pragma unroll
    for (int nt = 0; nt < 8; nt++) {
        m0 = fmaxf(m0, fmaxf(acc[nt][0], acc[nt][1]));
        m1 = fmaxf(m1, fmaxf(acc[nt][2], acc[nt][3]));
    }
    m0 = fmaxf(m0, __shfl_xor_sync(0xffffffffu, m0, 1));
    m0 = fmaxf(m0, __shfl_xor_sync(0xffffffffu, m0, 2));
    m1 = fmaxf(m1, __shfl_xor_sync(0xffffffffu, m1, 1));
    m1 = fmaxf(m1, __shfl_xor_sync(0xffffffffu, m1, 2));
    if (tig == 0) {
        Rmax[hh * 64 + r0] = m0;
        Rmax[hh * 64 + r1] = m1;
    }
    __syncthreads();
    float M0 = fmaxf(Rmax[r0], Rmax[64 + r0]) * C_LG2E;
    float M1 = fmaxf(Rmax[r1], Rmax[64 + r1]) * C_LG2E;

    uint32_t pf01[8], pf23[8];
    float s0 = 0.f, s1 = 0.f;
    #pragma unroll
    for (int nt = 0; nt < 8; nt++) {
        pf01[nt] = h2ex2(h2b(acc[nt][0] * C_LG2E - M0, acc[nt][1] * C_LG2E - M0));
        pf23[nt] = h2ex2(h2b(acc[nt][2] * C_LG2E - M1, acc[nt][3] * C_LG2E - M1));
        float2 f01 = __half22float2(*(__half2*)&pf01[nt]);
        float2 f23 = __half22float2(*(__half2*)&pf23[nt]);
        s0 += f01.x + f01.y;
        s1 += f23.x + f23.y;
    }
    s0 += __shfl_xor_sync(0xffffffffu, s0, 1);
    s0 += __shfl_xor_sync(0xffffffffu, s0, 2);
    s1 += __shfl_xor_sync(0xffffffffu, s1, 1);
    s1 += __shfl_xor_sync(0xffffffffu, s1, 2);
    if (tig == 0) {
        Rsum[hh * 64 + r0] = s0;
        Rsum[hh * 64 + r1] = s1;
    }

    // ---- PV partial: m16 x n64 over this warp's 64 keys, A from registers ----
    float pac[8][4];
    #pragma unroll
    for (int nt = 0; nt < 8; nt++)
        #pragma unroll
        for (int e = 0; e < 4; e++) pac[nt][e] = 0.f;
    {
        const uint32_t bvoff = vs_s +
            (uint32_t)(((nb0 + (lane & 7) + ((lane & 8) ? 8 : 0)) * AQ_STR
                        + ((lane & 16) ? 8 : 0)) * 2);
        #pragma unroll
        for (int j = 0; j < 4; j++) {
            uint32_t a[4] = { pf01[2 * j], pf23[2 * j], pf01[2 * j + 1], pf23[2 * j + 1] };
            uint32_t rowb = (uint32_t)(j * 16 * AQ_STR * 2);
            #pragma unroll
            for (int p = 0; p < 4; p++) {
                uint32_t bf[4];
                ldsm_x4_t(bf, bvoff + rowb + (uint32_t)(p * 16 * 2));
                mma_f16(pac[2 * p],     a, bf);
                mma_f16(pac[2 * p + 1], a, bf + 2);
            }
        }
    }

    // ---- combine partials across key-halves ----
    if (hh == 1) {
        float* pp = Pp + pair * 16 * PP_STR;
        #pragma unroll
        for (int nt = 0; nt < 8; nt++) {
            int c = nt * 8 + 2 * tig;
            *(float2*)(pp + grp * PP_STR + c)       = make_float2(pac[nt][0], pac[nt][1]);
            *(float2*)(pp + (grp + 8) * PP_STR + c) = make_float2(pac[nt][2], pac[nt][3]);
        }
    }
    __syncthreads();
    if (hh == 0) {
        float inv0 = 1.f / (Rsum[r0] + Rsum[64 + r0]);
        float inv1 = 1.f / (Rsum[r1] + Rsum[64 + r1]);
        const float* pp = Pp + pair * 16 * PP_STR;
        #pragma unroll
        for (int nt = 0; nt < 8; nt++) {
            int c = nt * 8 + 2 * tig;
            float2 o0 = *(const float2*)(pp + grp * PP_STR + c);
            float2 o1 = *(const float2*)(pp + (grp + 8) * PP_STR + c);
            *(__half2*)(Op + (size_t)r0 * DD + c) =
                __floats2half2_rn((pac[nt][0] + o0.x) * inv0, (pac[nt][1] + o0.y) * inv0);
            *(__half2*)(Op + (size_t)r1 * DD + c) =
                __floats2half2_rn((pac[nt][2] + o1.x) * inv1, (pac[nt][3] + o1.y) * inv1);
        }
    }
}

// ---------------- launch ----------------
#define SMEM_GEMM (4 * 128 * GS * 2)
#define MH (MTOK / 2)

extern "C" void kernel_launch(void* const* d_in, const int* in_sizes, int n_in,
                              void* d_out, int out_size) {
    const float* x       = (const float*)d_in[0];
    const float* f       = (const float*)d_in[1];
    const float* wq      = (const float*)d_in[2];
    const float* bq      = (const float*)d_in[3];
    const float* wk      = (const float*)d_in[4];
    const float* bk      = (const float*)d_in[5];
    const float* wv      = (const float*)d_in[6];
    const float* bv      = (const float*)d_in[7];
    const float* wo      = (const float*)d_in[8];
    const float* bo      = (const float*)d_in[9];
    const float* rw_w    = (const float*)d_in[10];
    const float* rw_b    = (const float*)d_in[11];
    const float* convk_w = (const float*)d_in[12];
    const float* convk_b = (const float*)d_in[13];
    const float* convv_w = (const float*)d_in[14];
    const float* convv_b = (const float*)d_in[15];
    const float* qn_g    = (const float*)d_in[16];
    const float* qn_b    = (const float*)d_in[17];
    const float* kn_g    = (const float*)d_in[18];
    const float* kn_b    = (const float*)d_in[19];
    const float* vn_g    = (const float*)d_in[20];
    const float* vn_b    = (const float*)d_in[21];
    float* out = (float*)d_out;

    float *kg, *vg, *fbqk, *fbv, *cvT, *ckT;
    __half *xf, *qkh, *qkn, *xn, *kgn, *vgn, *Q, *Kl, *Vl, *Kg, *Vg, *O;
    __half *fwqk, *fwv, *fwo, *frw;
    cudaGetSymbolAddress((void**)&kg,   g_kg);
    cudaGetSymbolAddress((void**)&vg,   g_vg);
    cudaGetSymbolAddress((void**)&xf,   g_xf);
    cudaGetSymbolAddress((void**)&qkh,  g_qkh);
    cudaGetSymbolAddress((void**)&qkn,  g_qkn);
    cudaGetSymbolAddress((void**)&xn,   g_xn);
    cudaGetSymbolAddress((void**)&kgn,  g_kgn);
    cudaGetSymbolAddress((void**)&vgn,  g_vgn);
    cudaGetSymbolAddress((void**)&Q,    g_Q);
    cudaGetSymbolAddress((void**)&Kl,   g_Kl);
    cudaGetSymbolAddress((void**)&Vl,   g_Vl);
    cudaGetSymbolAddress((void**)&Kg,   g_Kg);
    cudaGetSymbolAddress((void**)&Vg,   g_Vg);
    cudaGetSymbolAddress((void**)&O,    g_O);
    cudaGetSymbolAddress((void**)&fwqk, g_fwqk);
    cudaGetSymbolAddress((void**)&fbqk, g_fbqk);
    cudaGetSymbolAddress((void**)&fwv,  g_fwv);
    cudaGetSymbolAddress((void**)&fwo,  g_fwo);
    cudaGetSymbolAddress((void**)&frw,  g_frw);
    cudaGetSymbolAddress((void**)&fbv,  g_fbv);
    cudaGetSymbolAddress((void**)&cvT,  g_cvT);
    cudaGetSymbolAddress((void**)&ckT,  g_ckT);

    cudaFuncSetAttribute(attn_kernel, cudaFuncAttributeMaxDynamicSharedMemorySize,
                         ATTN_SMEM_BYTES);
    cudaFuncSetAttribute(mma_gemm<0,0>, cudaFuncAttributeMaxDynamicSharedMemorySize, SMEM_GEMM);
    cudaFuncSetAttribute(mma_gemm<1,1>, cudaFuncAttributeMaxDynamicSharedMemorySize, SMEM_GEMM);
    cudaFuncSetAttribute(mma_gemm<1,0>, cudaFuncAttributeMaxDynamicSharedMemorySize, SMEM_GEMM);
    cudaFuncSetAttribute(mma_gemm<2,0>, cudaFuncAttributeMaxDynamicSharedMemorySize, SMEM_GEMM);
    cudaFuncSetAttribute(mma_gemm<3,0>, cudaFuncAttributeMaxDynamicSharedMemorySize, SMEM_GEMM);

    cudaStream_t s1, s2;
    cudaStreamCreateWithFlags(&s1, cudaStreamNonBlocking);
    cudaStreamCreateWithFlags(&s2, cudaStreamNonBlocking);
    cudaEvent_t evFork, evFRW, evJoinV, evPrep, evRW0, evRW1, evQK1, evJoinKG, evA0, evO0;
    cudaEventCreateWithFlags(&evFork,   cudaEventDisableTiming);
    cudaEventCreateWithFlags(&evFRW,    cudaEventDisableTiming);
    cudaEventCreateWithFlags(&evJoinV,  cudaEventDisableTiming);
    cudaEventCreateWithFlags(&evPrep,   cudaEventDisableTiming);
    cudaEventCreateWithFlags(&evRW0,    cudaEventDisableTiming);
    cudaEventCreateWithFlags(&evRW1,    cudaEventDisableTiming);
    cudaEventCreateWithFlags(&evQK1,    cudaEventDisableTiming);
    cudaEventCreateWithFlags(&evJoinKG, cudaEventDisableTiming);
    cudaEventCreateWithFlags(&evA0,     cudaEventDisableTiming);
    cudaEventCreateWithFlags(&evO0,     cudaEventDisableTiming);

    cudaEventRecord(evFork, 0);
    cudaStreamWaitEvent(s1, evFork, 0);
    cudaStreamWaitEvent(s2, evFork, 0);

    // ---- s1: frw fold first, then x-side chain ----
    fold_w_kernel<<<80, 256, 0, s1>>>(rw_w, nullptr, nullptr, nullptr, frw, nullptr, INCC, INCC);
    cudaEventRecord(evFRW, s1);
    fold_w_kernel<<<64, 256, 0, s1>>>(wv, vn_g, vn_b, bv, fwv, fbv, DD, DD);
    fold_w_kernel<<<64, 256, 0, s1>>>(wo, nullptr, nullptr, nullptr, fwo, nullptr, DD, DD);
    fold_w_kernel<<<64, 256, 0, s1>>>(wq, qn_g, qn_b, bq, fwqk, fbqk, DD, INCC);
    fold_w_kernel<<<64, 256, 0, s1>>>(wk, kn_g, kn_b, bk, fwqk + (size_t)DD * INCC, fbqk + DD, DD, INCC);
    convT_kernel<<<(DD * 64) / 256, 256, 0, s1>>>(convv_w, cvT, DD);
    convT_kernel<<<(INCC * 64) / 256, 256, 0, s1>>>(convk_w, ckT, INCC);
    ln_norm_kernel<512><<<MTOK / 8, 256, 0, s1>>>(x, xn);
    dwconv_kernel<512,float><<<dim3(4, BT * GG), 128, 0, s1>>>(x, cvT, convv_b, vg);
    ln_norm_kernel<512><<<(BT * NGLOB) / 8, 256, 0, s1>>>(vg, vgn);
    mma_gemm<1,0><<<dim3(4, 256), 256, SMEM_GEMM, s1>>>(
        xn, fwv, fbv, nullptr, Vl, nullptr, MTOK, DD, DD, DD, 0);
    mma_gemm<2,0><<<dim3(4, 4), 256, SMEM_GEMM, s1>>>(
        vgn, fwv, fbv, nullptr, Vg, nullptr, BT * NGLOB, DD, DD, DD, 0);
    cudaEventRecord(evJoinV, s1);

    // ---- default stream: prep then rw half0 chain ----
    prep_xf_kernel<<<MTOK * INCC / 2048, 256>>>(x, f, xf);
    cudaEventRecord(evPrep, 0);

    cudaStreamWaitEvent(0, evFRW, 0);
    mma_gemm<0,0><<<dim3(5, 128), 256, SMEM_GEMM>>>(
        xf, frw, rw_b, nullptr, qkh, nullptr, MTOK, INCC, INCC, INCC, 0);
    cudaEventRecord(evRW0, 0);
    ln_norm_h_kernel<640><<<MH / 8, 256>>>(qkh, qkn, 0);
    mma_gemm<1,1><<<dim3(8, 128), 256, SMEM_GEMM>>>(
        qkn, fwqk, fbqk, nullptr, Q, Kl, MTOK, 2 * DD, INCC, DD, 0);

    // ---- s2: rw half1 chain ----
    cudaStreamWaitEvent(s2, evPrep, 0);
    cudaStreamWaitEvent(s2, evFRW, 0);
    mma_gemm<0,0><<<dim3(5, 128), 256, SMEM_GEMM, s2>>>(
        xf, frw, rw_b, nullptr, qkh, nullptr, MTOK, INCC, INCC, INCC, MH);
    cudaEventRecord(evRW1, s2);
    ln_norm_h_kernel<640><<<MH / 8, 256, 0, s2>>>(qkh, qkn, MH);
    mma_gemm<1,1><<<dim3(8, 128), 256, SMEM_GEMM, s2>>>(
        qkn, fwqk, fbqk, nullptr, Q, Kl, MTOK, 2 * DD, INCC, DD, MH);
    cudaEventRecord(evQK1, s2);

    // ---- s1: kg chain ----
    cudaStreamWaitEvent(s1, evRW0, 0);
    cudaStreamWaitEvent(s1, evRW1, 0);
    dwconv_kernel<640,__half><<<dim3(5, BT * GG), 128, 0, s1>>>(qkh, ckT, convk_b, kg);
    ln_norm_kernel<640><<<(BT * NGLOB) / 8, 256, 0, s1>>>(kg, kgn);
    mma_gemm<2,0><<<dim3(4, 4), 256, SMEM_GEMM, s1>>>(
        kgn, fwqk + (size_t)DD * INCC, fbqk + DD, nullptr, Kg, nullptr,
        BT * NGLOB, DD, INCC, DD, 0);
    cudaEventRecord(evJoinKG, s1);

    // ---- tail: staggered attention + out-projection ----
    cudaStreamWaitEvent(0, evJoinV, 0);
    cudaStreamWaitEvent(0, evJoinKG, 0);
    attn_kernel<<<BT * GG * NHEAD / 2, 256, ATTN_SMEM_BYTES>>>(Q, Kl, Kg, Vl, Vg, O, 0);
    cudaEventRecord(evA0, 0);
    cudaStreamWaitEvent(0, evQK1, 0);
    attn_kernel<<<BT * GG * NHEAD / 2, 256, ATTN_SMEM_BYTES>>>(Q, Kl, Kg, Vl, Vg, O,
                                                               BT * GG * NHEAD / 2);
    cudaStreamWaitEvent(s2, evA0, 0);
    cudaStreamWaitEvent(s2, evJoinV, 0);
    mma_gemm<3,0><<<dim3(4, 128), 256, SMEM_GEMM, s2>>>(
        O, fwo, bo, out, nullptr, nullptr, MTOK, DD, DD, DD, 0);
    cudaEventRecord(evO0, s2);
    mma_gemm<3,0><<<dim3(4, 128), 256, SMEM_GEMM>>>(
        O, fwo, bo, out, nullptr, nullptr, MTOK, DD, DD, DD, MH);
    cudaStreamWaitEvent(0, evO0, 0);

    cudaEventDestroy(evFork);
    cudaEventDestroy(evFRW);
    cudaEventDestroy(evJoinV);
    cudaEventDestroy(evPrep);
    cudaEventDestroy(evRW0);
    cudaEventDestroy(evRW1);
    cudaEventDestroy(evQK1);
    cudaEventDestroy(evJoinKG);
    cudaEventDestroy(evA0);
    cudaEventDestroy(evO0);
    cudaStreamDestroy(s1);
    cudaStreamDestroy(s2);
}

// round 17
// speedup vs baseline: 1.1325x; 1.0065x over previous
#include <cuda_runtime.h>
#include <cuda_fp16.h>
#include <cstdint>

// ---------------- problem constants ----------------
#define BT     8
#define NPIX   4096
#define DD     512
#define CFF    128
#define INCC   640
#define GG     64
#define NWIN   64
#define NGLOB  64
#define NHEAD  8
#define DHH    64
#define MTOK   32768

// ---------------- scratch ----------------
__device__ float  g_kg [BT*NGLOB*INCC];
__device__ float  g_vg [BT*NGLOB*DD];
__device__ __half g_xf [MTOK*INCC];
__device__ __half g_qkh[MTOK*INCC];
__device__ __half g_qkn[MTOK*INCC];
__device__ __half g_xn [MTOK*DD];
__device__ __half g_kgn[BT*NGLOB*INCC];
__device__ __half g_vgn[BT*NGLOB*DD];
__device__ __half g_Q  [MTOK*DD];
__device__ __half g_Kl [MTOK*DD];
__device__ __half g_Vl [MTOK*DD];
__device__ __half g_Kg [BT*NGLOB*DD];
__device__ __half g_Vg [BT*NGLOB*DD];
__device__ __half g_O  [MTOK*DD];
__device__ __half g_fwqk[2*DD*INCC];
__device__ float  g_fbqk[2*DD];
__device__ __half g_fwv[DD*DD];
__device__ __half g_fwo[DD*DD];
__device__ __half g_frw[INCC*INCC];
__device__ float  g_fbv[DD];
__device__ float  g_cvT[64*DD];
__device__ float  g_ckT[64*INCC];

// ---------------- helpers ----------------
__device__ __forceinline__ int win_map(int r) {
    int b = r >> 12;
    int p = r & 4095;
    int h = p >> 6, w = p & 63;
    int g = ((h >> 3) << 3) | (w >> 3);
    int n = ((h & 7) << 3) | (w & 7);
    return (((b << 6) | g) << 6) | n;
}

__device__ __forceinline__ uint32_t h2b(float a, float b) {
    __half2 h = __floats2half2_rn(a, b);
    return *(uint32_t*)&h;
}
__device__ __forceinline__ uint32_t h2ex2(uint32_t t) {
    uint32_t d;
    asm("ex2.approx.f16x2 %0, %1;" : "=r"(d) : "r"(t));
    return d;
}
__device__ __forceinline__ uint32_t h2tanh(uint32_t t) {
    uint32_t d;
    asm("tanh.approx.f16x2 %0, %1;" : "=r"(d) : "r"(t));
    return d;
}

__device__ __forceinline__ void mma_f16(float* d, const uint32_t* a, const uint32_t* b) {
    asm volatile(
        "mma.sync.aligned.m16n8k16.row.col.f32.f16.f16.f32 "
        "{%0,%1,%2,%3}, {%4,%5,%6,%7}, {%8,%9}, {%0,%1,%2,%3};"
        : "+f"(d[0]), "+f"(d[1]), "+f"(d[2]), "+f"(d[3])
        : "r"(a[0]), "r"(a[1]), "r"(a[2]), "r"(a[3]), "r"(b[0]), "r"(b[1]));
}

__device__ __forceinline__ void ldsm_x4(uint32_t* r, uint32_t addr) {
    asm volatile("ldmatrix.sync.aligned.m8n8.x4.shared.b16 {%0,%1,%2,%3}, [%4];"
                 : "=r"(r[0]), "=r"(r[1]), "=r"(r[2]), "=r"(r[3]) : "r"(addr));
}
__device__ __forceinline__ void ldsm_x4_t(uint32_t* r, uint32_t addr) {
    asm volatile("ldmatrix.sync.aligned.m8n8.x4.trans.shared.b16 {%0,%1,%2,%3}, [%4];"
                 : "=r"(r[0]), "=r"(r[1]), "=r"(r[2]), "=r"(r[3]) : "r"(addr));
}

#define CP_ASYNC16(dst, src) \
    asm volatile("cp.async.ca.shared.global [%0], [%1], 16;" :: "r"(dst), "l"(src))
#define CP_COMMIT() asm volatile("cp.async.commit_group;" ::: "memory")
#define CP_WAIT0()  asm volatile("cp.async.wait_group 0;" ::: "memory")

// ---------------- fused weight fold (5 weights, one launch) ----------------
__device__ __forceinline__ void fold_rows(const float* __restrict__ W,
                                          const float* __restrict__ gamma,
                                          const float* __restrict__ beta,
                                          const float* __restrict__ b,
                                          __half* __restrict__ Wo,
                                          float* __restrict__ bo,
                                          int N, int K, int blk, int wid, int lane) {
    int n = blk * 8 + wid;
    if (n >= N) return;
    const float* wr = W + (size_t)n * K;
    __half* wor = Wo + (size_t)n * K;
    float acc = 0.f;
    for (int k = lane; k < K; k += 32) {
        float w = wr[k];
        if (beta) acc += beta[k] * w;
        wor[k] = __float2half(gamma ? w * gamma[k] : w);
    }
    if (beta) {
        #pragma unroll
        for (int o = 16; o; o >>= 1) acc += __shfl_xor_sync(0xffffffffu, acc, o);
        if (lane == 0) bo[n] = b[n] + acc;
    }
}

__global__ __launch_bounds__(256)
void fold_all_kernel(const float* __restrict__ wq, const float* __restrict__ qn_g,
                     const float* __restrict__ qn_b, const float* __restrict__ bq,
                     const float* __restrict__ wk, const float* __restrict__ kn_g,
                     const float* __restrict__ kn_b, const float* __restrict__ bk,
                     const float* __restrict__ wv, const float* __restrict__ vn_g,
                     const float* __restrict__ vn_b, const float* __restrict__ bv,
                     const float* __restrict__ wo, const float* __restrict__ rw_w,
                     __half* __restrict__ fwqk, float* __restrict__ fbqk,
                     __half* __restrict__ fwv, float* __restrict__ fbv,
                     __half* __restrict__ fwo, __half* __restrict__ frw) {
    int blk = blockIdx.x;
    int wid = threadIdx.x >> 5, lane = threadIdx.x & 31;
    if (blk < 64) {
        fold_rows(wq, qn_g, qn_b, bq, fwqk, fbqk, DD, INCC, blk, wid, lane);
    } else if (blk < 128) {
        fold_rows(wk, kn_g, kn_b, bk, fwqk + (size_t)DD * INCC, fbqk + DD,
                  DD, INCC, blk - 64, wid, lane);
    } else if (blk < 192) {
        fold_rows(wv, vn_g, vn_b, bv, fwv, fbv, DD, DD, blk - 128, wid, lane);
    } else if (blk < 256) {
        fold_rows(wo, nullptr, nullptr, nullptr, fwo, nullptr, DD, DD, blk - 192, wid, lane);
    } else {
        fold_rows(rw_w, nullptr, nullptr, nullptr, frw, nullptr, INCC, INCC,
                  blk - 256, wid, lane);
    }
}

// ---------------- conv weight transpose ----------------
__global__ __launch_bounds__(256)
void convT_kernel(const float* __restrict__ W, float* __restrict__ Wt, int C) {
    int idx = blockIdx.x * 256 + threadIdx.x;
    if (idx >= C * 64) return;
    int c = idx >> 6, k = idx & 63;
    Wt[k * C + c] = W[idx];
}

// ---------------- raw concat(x,f) -> half ----------------
__global__ __launch_bounds__(256)
void prep_xf_kernel(const float* __restrict__ x, const float* __restrict__ f,
                    __half* __restrict__ xf) {
    size_t idx = ((size_t)blockIdx.x * 256 + threadIdx.x) * 8;
    int r = (int)(idx / INCC);
    int c = (int)(idx % INCC);
    const float* src = (c < 512) ? (x + (size_t)r * 512 + c)
                                 : (f + (size_t)r * 128 + (c - 512));
    float4 a = *(const float4*)src;
    float4 b = *(const float4*)(src + 4);
    uint4 o;
    o.x = h2b(a.x, a.y); o.y = h2b(a.z, a.w);
    o.z = h2b(b.x, b.y); o.w = h2b(b.z, b.w);
    *(uint4*)(xf + idx) = o;
}

// ---------------- fused LN (fp32 input) ----------------
template<int K>
__global__ __launch_bounds__(256)
void ln_norm_kernel(const float* __restrict__ X, __half* __restrict__ Xn) {
    const int NSEG = K / 128;
    int row = blockIdx.x * 8 + (threadIdx.x >> 5);
    int lane = threadIdx.x & 31;
    const float* xr = X + (size_t)row * K;
    float4 v[NSEG];
    float s = 0.f, ss = 0.f;
    #pragma unroll
    for (int i = 0; i < NSEG; i++) {
        v[i] = *(const float4*)(xr + lane * 4 + i * 128);
        s  += v[i].x + v[i].y + v[i].z + v[i].w;
        ss += v[i].x * v[i].x + v[i].y * v[i].y + v[i].z * v[i].z + v[i].w * v[i].w;
    }
    #pragma unroll
    for (int o = 16; o; o >>= 1) {
        s  += __shfl_xor_sync(0xffffffffu, s, o);
        ss += __shfl_xor_sync(0xffffffffu, ss, o);
    }
    float mean = s / K;
    float rstd = rsqrtf(ss / K - mean * mean + 1e-5f);
    __half* xo = Xn + (size_t)row * K;
    #pragma unroll
    for (int i = 0; i < NSEG; i++) {
        uint2 o;
        o.x = h2b((v[i].x - mean) * rstd, (v[i].y - mean) * rstd);
        o.y = h2b((v[i].z - mean) * rstd, (v[i].w - mean) * rstd);
        *(uint2*)(xo + lane * 4 + i * 128) = o;
    }
}

// ---------------- fused LN (half input) ----------------
template<int K>
__global__ __launch_bounds__(256)
void ln_norm_h_kernel(const __half* __restrict__ X, __half* __restrict__ Xn, int row0) {
    const int NSEG = K / 128;
    int row = row0 + blockIdx.x * 8 + (threadIdx.x >> 5);
    int lane = threadIdx.x & 31;
    const __half* xr = X + (size_t)row * K;
    float v[NSEG][4];
    float s = 0.f, ss = 0.f;
    #pragma unroll
    for (int i = 0; i < NSEG; i++) {
        uint2 p = *(const uint2*)(xr + lane * 4 + i * 128);
        __half2 h0 = *(__half2*)&p.x;
        __half2 h1 = *(__half2*)&p.y;
        v[i][0] = __half2float(h0.x); v[i][1] = __half2float(h0.y);
        v[i][2] = __half2float(h1.x); v[i][3] = __half2float(h1.y);
        #pragma unroll
        for (int j = 0; j < 4; j++) { s += v[i][j]; ss += v[i][j] * v[i][j]; }
    }
    #pragma unroll
    for (int o = 16; o; o >>= 1) {
        s  += __shfl_xor_sync(0xffffffffu, s, o);
        ss += __shfl_xor_sync(0xffffffffu, ss, o);
    }
    float mean = s / K;
    float rstd = rsqrtf(ss / K - mean * mean + 1e-5f);
    __half* xo = Xn + (size_t)row * K;
    #pragma unroll
    for (int i = 0; i < NSEG; i++) {
        uint2 o;
        o.x = h2b((v[i][0] - mean) * rstd, (v[i][1] - mean) * rstd);
        o.y = h2b((v[i][2] - mean) * rstd, (v[i][3] - mean) * rstd);
        *(uint2*)(xo + lane * 4 + i * 128) = o;
    }
}

// ---------------- depthwise conv ----------------
template<int C, typename T>
__global__ __launch_bounds__(128)
void dwconv_kernel(const T* __restrict__ X, const float* __restrict__ Wt,
                   const float* __restrict__ bc, float* __restrict__ out) {
    int bw = blockIdx.y;
    int c = blockIdx.x * 128 + threadIdx.x;
    int b = bw >> 6;
    int g = bw & 63;
    int gh = g >> 3, gw = g & 7;
    const T* xb = X + ((size_t)b * NPIX + (size_t)(gh * 8) * 64 + gw * 8) * C + c;
    float s = bc[c];
    #pragma unroll
    for (int i = 0; i < 8; i++)
        #pragma unroll
        for (int j = 0; j < 8; j++)
            s += (float)xb[(size_t)(i * 64 + j) * C] * Wt[(i * 8 + j) * C + c];
    out[(size_t)bw * C + c] = s;
}

// ---------------- fp16 mma GEMM, 2-stage cp.async ----------------
#define GS 72
template<int MODE, int SPLIT>
__global__ __launch_bounds__(256)
void mma_gemm(const __half* __restrict__ A, const __half* __restrict__ W,
              const float* __restrict__ bias,
              float* __restrict__ Cf, __half* __restrict__ Ch, __half* __restrict__ Ch2,
              int M, int N, int K, int ldc, int m_off) {
    extern __shared__ __half sh[];
    __half* As = sh;
    __half* Bs = sh + 2 * 128 * GS;

    const int tid = threadIdx.x;
    const int m0 = blockIdx.y * 128 + m_off;
    const int n0 = blockIdx.x * 128;
    const int q = tid & 7;
    const int lrow = tid >> 3;
    const int lane = tid & 31, grp = lane >> 2, tig = lane & 3;
    const int w = tid >> 5, mblk = (w & 3) * 32, nblk = (w >> 2) * 64;
    const int NC = K >> 6;

    const uint32_t as_s = (uint32_t)__cvta_generic_to_shared(As);
    const uint32_t bs_s = (uint32_t)__cvta_generic_to_shared(Bs);

    const uint32_t aoff0 = (uint32_t)(((mblk + (lane & 15)) * GS + (lane >> 4) * 8) * 2);
    const uint32_t aoff1 = aoff0 + (uint32_t)(16 * GS * 2);
    const uint32_t boff  = (uint32_t)(((nblk + (lane & 7) + ((lane & 16) ? 8 : 0)) * GS
                                       + ((lane & 8) ? 8 : 0)) * 2);

    int arow[4];
    #pragma unroll
    for (int i = 0; i < 4; i++) {
        int r = m0 + lrow + i * 32;
        arow[i] = (MODE == 3) ? win_map(r) : r;
    }

    float acc[2][8][4];
    #pragma unroll
    for (int mt = 0; mt < 2; mt++)
        #pragma unroll
        for (int nt = 0; nt < 8; nt++)
            #pragma unroll
            for (int e = 0; e < 4; e++) acc[mt][nt][e] = 0.f;

    auto issue = [&](int ch, int buf) {
        int gk = (ch << 6) + q * 8;
        #pragma unroll
        for (int i = 0; i < 4; i++) {
            int r = lrow + i * 32;
            CP_ASYNC16(as_s + (uint32_t)(((buf * 128 + r) * GS + q * 8) * 2),
                       A + (size_t)arow[i] * K + gk);
            CP_ASYNC16(bs_s + (uint32_t)(((buf * 128 + r) * GS + q * 8) * 2),
                       W + (size_t)(n0 + r) * K + gk);
        }
        CP_COMMIT();
    };
    auto compute = [&](int buf) {
        uint32_t abase = as_s + (uint32_t)(buf * 128 * GS * 2);
        uint32_t bbase = bs_s + (uint32_t)(buf * 128 * GS * 2);
        #pragma unroll
        for (int k16 = 0; k16 < 4; k16++) {
            uint32_t kb = (uint32_t)(k16 * 32);
            uint32_t af0[4], af1[4];
            ldsm_x4(af0, abase + aoff0 + kb);
            ldsm_x4(af1, abase + aoff1 + kb);
            #pragma unroll
            for (int p = 0; p < 4; p++) {
                uint32_t bf[4];
                ldsm_x4(bf, bbase + boff + (uint32_t)(p * 16 * GS * 2) + kb);
                mma_f16(acc[0][2 * p],     af0, bf);
                mma_f16(acc[1][2 * p],     af1, bf);
                mma_f16(acc[0][2 * p + 1], af0, bf + 2);
                mma_f16(acc[1][2 * p + 1], af1, bf + 2);
            }
        }
    };

    issue(0, 0);
    CP_WAIT0();
    __syncthreads();

    for (int ch = 0; ch < NC; ch++) {
        int buf = ch & 1;
        int nx = ch + 1;
        if (nx < NC) issue(nx, buf ^ 1);
        compute(buf);
        if (nx < NC) CP_WAIT0();
        __syncthreads();
    }

    const __half2 hhalf = __floats2half2_rn(0.5f, 0.5f);
    #pragma unroll
    for (int mt = 0; mt < 2; mt++) {
        #pragma unroll
        for (int hr = 0; hr < 2; hr++) {
            int r = m0 + mblk + mt * 16 + grp + hr * 8;
            size_t orow = (MODE == 1) ? (size_t)win_map(r) : (size_t)r;
            #pragma unroll
            for (int nt = 0; nt < 8; nt++) {
                int c = n0 + nblk + nt * 8 + 2 * tig;
                float y0 = acc[mt][nt][hr * 2 + 0] + bias[c];
                float y1 = acc[mt][nt][hr * 2 + 1] + bias[c + 1];
                if (MODE == 0) {
                    __half2 a01 = *(const __half2*)(A + (size_t)r * K + c);
                    uint32_t th = h2tanh(h2b(y0 * 0.5f, y1 * 0.5f));
                    __half2 sig = __hfma2(*(__half2*)&th, hhalf, hhalf);
                    *(__half2*)(Ch + orow * (size_t)ldc + c) = __hmul2(a01, sig);
                } else if (MODE == 3) {
                    *(float2*)(Cf + orow * (size_t)ldc + c) = make_float2(y0, y1);
                } else {
                    __half* base = Ch;
                    int cc = c;
                    if (SPLIT) { base = (c < 512) ? Ch : Ch2; cc = c & 511; }
                    *(__half2*)(base + orow * (size_t)ldc + cc) = __floats2half2_rn(y0, y1);
                }
            }
        }
    }
}

// ---------------- attention: register softmax + register-fragment PV ----------------
#define AQ_STR 72
#define PP_STR 68
#define ATTN_SMEM_BYTES ((64*AQ_STR + 128*AQ_STR + 128*AQ_STR) * 2 + 4*16*PP_STR*4 + 2*128*4)
#define C_LG2E 0.18033688f

__global__ __launch_bounds__(256)
void attn_kernel(const __half* __restrict__ Q, const __half* __restrict__ Kl,
                 const __half* __restrict__ Kg, const __half* __restrict__ Vl,
                 const __half* __restrict__ Vg, __half* __restrict__ O, int bid_off) {
    extern __shared__ char smraw[];
    __half* Qs = (__half*)smraw;
    __half* Ks = Qs + 64 * AQ_STR;
    __half* Vs = Ks + 128 * AQ_STR;
    float* Pp  = (float*)(Vs + 128 * AQ_STR);
    float* Rmax = Pp + 4 * 16 * PP_STR;
    float* Rsum = Rmax + 128;

    int bid = blockIdx.x + bid_off;
    int b = bid >> 9;
    int rem = bid & 511;
    int g = rem >> 3;
    int h = rem & 7;

    size_t wbase = ((size_t)(b * GG + g) * NWIN) * DD + (size_t)h * DHH;
    size_t gbase = ((size_t)b * NGLOB) * DD + (size_t)h * DHH;
    const __half* Qp  = Q  + wbase;
    const __half* Klp = Kl + wbase;
    const __half* Vlp = Vl + wbase;
    const __half* Kgp = Kg + gbase;
    const __half* Vgp = Vg + gbase;
    __half* Op = O + wbase;

    int tid = threadIdx.x;
    const uint32_t qs_s = (uint32_t)__cvta_generic_to_shared(Qs);
    const uint32_t ks_s = (uint32_t)__cvta_generic_to_shared(Ks);
    const uint32_t vs_s = (uint32_t)__cvta_generic_to_shared(Vs);

    for (int e = tid; e < 64 * 8; e += 256) {
        int m = e >> 3, sg = e & 7;
        CP_ASYNC16(qs_s + (uint32_t)((m * AQ_STR + sg * 8) * 2), Qp + (size_t)m * DD + sg * 8);
    }
    for (int e = tid; e < 128 * 8; e += 256) {
        int kk = e >> 3, sg = e & 7;
        const __half* ksrc = (kk < 64) ? (Klp + (size_t)kk * DD)
                                       : (Kgp + (size_t)(kk - 64) * DD);
        CP_ASYNC16(ks_s + (uint32_t)((kk * AQ_STR + sg * 8) * 2), ksrc + sg * 8);
        const __half* vsrc = (kk < 64) ? (Vlp + (size_t)kk * DD)
                                       : (Vgp + (size_t)(kk - 64) * DD);
        CP_ASYNC16(vs_s + (uint32_t)((kk * AQ_STR + sg * 8) * 2), vsrc + sg * 8);
    }
    CP_COMMIT();
    CP_WAIT0();
    __syncthreads();

    int w = tid >> 5, lane = tid & 31, grp = lane >> 2, tig = lane & 3;
    int mrow = (w & 3) * 16;
    int hh = w >> 2;
    int nb0 = hh * 64;
    int r0 = mrow + grp, r1 = r0 + 8;
    int pair = w & 3;

    float acc[8][4];
    {
        const uint32_t aoff = qs_s +
            (uint32_t)(((mrow + (lane & 15)) * AQ_STR + (lane >> 4) * 8) * 2);
        const uint32_t boff = ks_s +
            (uint32_t)(((nb0 + (lane & 7) + ((lane & 16) ? 8 : 0)) * AQ_STR
                        + ((lane & 8) ? 8 : 0)) * 2);
        #pragma unroll
        for (int nt = 0; nt < 8; nt++)
            #pragma unroll
            for (int e = 0; e < 4; e++) acc[nt][e] = 0.f;
        #pragma unroll
        for (int k16 = 0; k16 < 4; k16++) {
            uint32_t kb = (uint32_t)(k16 * 32);
            uint32_t af[4];
            ldsm_x4(af, aoff + kb);
            #pragma unroll
            for (int p = 0; p < 4; p++) {
                uint32_t bf[4];
                ldsm_x4(bf, boff + (uint32_t)(p * 16 * AQ_STR * 2) + kb);
                mma_f16(acc[2 * p],     af, bf);
                mma_f16(acc[2 * p + 1], af, bf + 2);
            }
        }
    }

    float m0 = -1e30f, m1 = -1e30f;
    #pragma unroll
    for (int nt = 0; nt < 8; nt++) {
        m0 = fmaxf(m0, fmaxf(acc[nt][0], acc[nt][1]));
        m1 = fmaxf(m1, fmaxf(acc[nt][2], acc[nt][3]));
    }
    m0 = fmaxf(m0, __shfl_xor_sync(0xffffffffu, m0, 1));
    m0 = fmaxf(m0, __shfl_xor_sync(0xffffffffu, m0, 2));
    m1 = fmaxf(m1, __shfl_xor_sync(0xffffffffu, m1, 1));
    m1 = fmaxf(m1, __shfl_xor_sync(0xffffffffu, m1, 2));
    if (tig == 0) {
        Rmax[hh * 64 + r0] = m0;
        Rmax[hh * 64 + r1] = m1;
    }
    __syncthreads();
    float M0 = fmaxf(Rmax[r0], Rmax[64 + r0]) * C_LG2E;
    float M1 = fmaxf(Rmax[r1], Rmax[64 + r1]) * C_LG2E;

    uint32_t pf01[8], pf23[8];
    float s0 = 0.f, s1 = 0.f;
    #pragma unroll
    for (int nt = 0; nt < 8; nt++) {
        pf01[nt] = h2ex2(h2b(acc[nt][0] * C_LG2E - M0, acc[nt][1] * C_LG2E - M0));
        pf23[nt] = h2ex2(h2b(acc[nt][2] * C_LG2E - M1, acc[nt][3] * C_LG2E - M1));
        float2 f01 = __half22float2(*(__half2*)&pf01[nt]);
        float2 f23 = __half22float2(*(__half2*)&pf23[nt]);
        s0 += f01.x + f01.y;
        s1 += f23.x + f23.y;
    }
    s0 += __shfl_xor_sync(0xffffffffu, s0, 1);
    s0 += __shfl_xor_sync(0xffffffffu, s0, 2);
    s1 += __shfl_xor_sync(0xffffffffu, s1, 1);
    s1 += __shfl_xor_sync(0xffffffffu, s1, 2);
    if (tig == 0) {
        Rsum[hh * 64 + r0] = s0;
        Rsum[hh * 64 + r1] = s1;
    }

    float pac[8][4];
    #pragma unroll
    for (int nt = 0; nt < 8; nt++)
        #pragma unroll
        for (int e = 0; e < 4; e++) pac[nt][e] = 0.f;
    {
        const uint32_t bvoff = vs_s +
            (uint32_t)(((nb0 + (lane & 7) + ((lane & 8) ? 8 : 0)) * AQ_STR
                        + ((lane & 16) ? 8 : 0)) * 2);
        #pragma unroll
        for (int j = 0; j < 4; j++) {
            uint32_t a[4] = { pf01[2 * j], pf23[2 * j], pf01[2 * j + 1], pf23[2 * j + 1] };
            uint32_t rowb = (uint32_t)(j * 16 * AQ_STR * 2);
            #pragma unroll
            for (int p = 0; p < 4; p++) {
                uint32_t bf[4];
                ldsm_x4_t(bf, bvoff + rowb + (uint32_t)(p * 16 * 2));
                mma_f16(pac[2 * p],     a, bf);
                mma_f16(pac[2 * p + 1], a, bf + 2);
            }
        }
    }

    if (hh == 1) {
        float* pp = Pp + pair * 16 * PP_STR;
        #pragma unroll
        for (int nt = 0; nt < 8; nt++) {
            int c = nt * 8 + 2 * tig;
            *(float2*)(pp + grp * PP_STR + c)       = make_float2(pac[nt][0], pac[nt][1]);
            *(float2*)(pp + (grp + 8) * PP_STR + c) = make_float2(pac[nt][2], pac[nt][3]);
        }
    }
    __syncthreads();
    if (hh == 0) {
        float inv0 = 1.f / (Rsum[r0] + Rsum[64 + r0]);
        float inv1 = 1.f / (Rsum[r1] + Rsum[64 + r1]);
        const float* pp = Pp + pair * 16 * PP_STR;
        #pragma unroll
        for (int nt = 0; nt < 8; nt++) {
            int c = nt * 8 + 2 * tig;
            float2 o0 = *(const float2*)(pp + grp * PP_STR + c);
            float2 o1 = *(const float2*)(pp + (grp + 8) * PP_STR + c);
            *(__half2*)(Op + (size_t)r0 * DD + c) =
                __floats2half2_rn((pac[nt][0] + o0.x) * inv0, (pac[nt][1] + o0.y) * inv0);
            *(__half2*)(Op + (size_t)r1 * DD + c) =
                __floats2half2_rn((pac[nt][2] + o1.x) * inv1, (pac[nt][3] + o1.y) * inv1);
        }
    }
}

// ---------------- launch ----------------
#define SMEM_GEMM (4 * 128 * GS * 2)
#define MH (MTOK / 2)

extern "C" void kernel_launch(void* const* d_in, const int* in_sizes, int n_in,
                              void* d_out, int out_size) {
    const float* x       = (const float*)d_in[0];
    const float* f       = (const float*)d_in[1];
    const float* wq      = (const float*)d_in[2];
    const float* bq      = (const float*)d_in[3];
    const float* wk      = (const float*)d_in[4];
    const float* bk      = (const float*)d_in[5];
    const float* wv      = (const float*)d_in[6];
    const float* bv      = (const float*)d_in[7];
    const float* wo      = (const float*)d_in[8];
    const float* bo      = (const float*)d_in[9];
    const float* rw_w    = (const float*)d_in[10];
    const float* rw_b    = (const float*)d_in[11];
    const float* convk_w = (const float*)d_in[12];
    const float* convk_b = (const float*)d_in[13];
    const float* convv_w = (const float*)d_in[14];
    const float* convv_b = (const float*)d_in[15];
    const float* qn_g    = (const float*)d_in[16];
    const float* qn_b    = (const float*)d_in[17];
    const float* kn_g    = (const float*)d_in[18];
    const float* kn_b    = (const float*)d_in[19];
    const float* vn_g    = (const float*)d_in[20];
    const float* vn_b    = (const float*)d_in[21];
    float* out = (float*)d_out;

    float *kg, *vg, *fbqk, *fbv, *cvT, *ckT;
    __half *xf, *qkh, *qkn, *xn, *kgn, *vgn, *Q, *Kl, *Vl, *Kg, *Vg, *O;
    __half *fwqk, *fwv, *fwo, *frw;
    cudaGetSymbolAddress((void**)&kg,   g_kg);
    cudaGetSymbolAddress((void**)&vg,   g_vg);
    cudaGetSymbolAddress((void**)&xf,   g_xf);
    cudaGetSymbolAddress((void**)&qkh,  g_qkh);
    cudaGetSymbolAddress((void**)&qkn,  g_qkn);
    cudaGetSymbolAddress((void**)&xn,   g_xn);
    cudaGetSymbolAddress((void**)&kgn,  g_kgn);
    cudaGetSymbolAddress((void**)&vgn,  g_vgn);
    cudaGetSymbolAddress((void**)&Q,    g_Q);
    cudaGetSymbolAddress((void**)&Kl,   g_Kl);
    cudaGetSymbolAddress((void**)&Vl,   g_Vl);
    cudaGetSymbolAddress((void**)&Kg,   g_Kg);
    cudaGetSymbolAddress((void**)&Vg,   g_Vg);
    cudaGetSymbolAddress((void**)&O,    g_O);
    cudaGetSymbolAddress((void**)&fwqk, g_fwqk);
    cudaGetSymbolAddress((void**)&fbqk, g_fbqk);
    cudaGetSymbolAddress((void**)&fwv,  g_fwv);
    cudaGetSymbolAddress((void**)&fwo,  g_fwo);
    cudaGetSymbolAddress((void**)&frw,  g_frw);
    cudaGetSymbolAddress((void**)&fbv,  g_fbv);
    cudaGetSymbolAddress((void**)&cvT,  g_cvT);
    cudaGetSymbolAddress((void**)&ckT,  g_ckT);

    cudaFuncSetAttribute(attn_kernel, cudaFuncAttributeMaxDynamicSharedMemorySize,
                         ATTN_SMEM_BYTES);
    cudaFuncSetAttribute(mma_gemm<0,0>, cudaFuncAttributeMaxDynamicSharedMemorySize, SMEM_GEMM);
    cudaFuncSetAttribute(mma_gemm<1,1>, cudaFuncAttributeMaxDynamicSharedMemorySize, SMEM_GEMM);
    cudaFuncSetAttribute(mma_gemm<1,0>, cudaFuncAttributeMaxDynamicSharedMemorySize, SMEM_GEMM);
    cudaFuncSetAttribute(mma_gemm<2,0>, cudaFuncAttributeMaxDynamicSharedMemorySize, SMEM_GEMM);
    cudaFuncSetAttribute(mma_gemm<3,0>, cudaFuncAttributeMaxDynamicSharedMemorySize, SMEM_GEMM);

    cudaStream_t s1, s2;
    cudaStreamCreateWithFlags(&s1, cudaStreamNonBlocking);
    cudaStreamCreateWithFlags(&s2, cudaStreamNonBlocking);
    cudaEvent_t evFork, evFold, evJoinV, evPrep, evRW0, evRW1, evQK1, evJoinKG, evEnd;
    cudaEventCreateWithFlags(&evFork,   cudaEventDisableTiming);
    cudaEventCreateWithFlags(&evFold,   cudaEventDisableTiming);
    cudaEventCreateWithFlags(&evJoinV,  cudaEventDisableTiming);
    cudaEventCreateWithFlags(&evPrep,   cudaEventDisableTiming);
    cudaEventCreateWithFlags(&evRW0,    cudaEventDisableTiming);
    cudaEventCreateWithFlags(&evRW1,    cudaEventDisableTiming);
    cudaEventCreateWithFlags(&evQK1,    cudaEventDisableTiming);
    cudaEventCreateWithFlags(&evJoinKG, cudaEventDisableTiming);
    cudaEventCreateWithFlags(&evEnd,    cudaEventDisableTiming);

    cudaEventRecord(evFork, 0);
    cudaStreamWaitEvent(s1, evFork, 0);
    cudaStreamWaitEvent(s2, evFork, 0);

    // ---- s1: fused weight fold (all 5) + conv transposes, then x-side chain ----
    fold_all_kernel<<<336, 256, 0, s1>>>(wq, qn_g, qn_b, bq, wk, kn_g, kn_b, bk,
                                         wv, vn_g, vn_b, bv, wo, rw_w,
                                         fwqk, fbqk, fwv, fbv, fwo, frw);
    cudaEventRecord(evFold, s1);
    convT_kernel<<<(DD * 64) / 256, 256, 0, s1>>>(convv_w, cvT, DD);
    convT_kernel<<<(INCC * 64) / 256, 256, 0, s1>>>(convk_w, ckT, INCC);
    ln_norm_kernel<512><<<MTOK / 8, 256, 0, s1>>>(x, xn);
    dwconv_kernel<512,float><<<dim3(4, BT * GG), 128, 0, s1>>>(x, cvT, convv_b, vg);
    ln_norm_kernel<512><<<(BT * NGLOB) / 8, 256, 0, s1>>>(vg, vgn);
    mma_gemm<1,0><<<dim3(4, 256), 256, SMEM_GEMM, s1>>>(
        xn, fwv, fbv, nullptr, Vl, nullptr, MTOK, DD, DD, DD, 0);
    mma_gemm<2,0><<<dim3(4, 4), 256, SMEM_GEMM, s1>>>(
        vgn, fwv, fbv, nullptr, Vg, nullptr, BT * NGLOB, DD, DD, DD, 0);
    cudaEventRecord(evJoinV, s1);

    // ---- default stream: prep then rw half0 chain ----
    prep_xf_kernel<<<MTOK * INCC / 2048, 256>>>(x, f, xf);
    cudaEventRecord(evPrep, 0);

    cudaStreamWaitEvent(0, evFold, 0);
    mma_gemm<0,0><<<dim3(5, 128), 256, SMEM_GEMM>>>(
        xf, frw, rw_b, nullptr, qkh, nullptr, MTOK, INCC, INCC, INCC, 0);
    cudaEventRecord(evRW0, 0);
    ln_norm_h_kernel<640><<<MH / 8, 256>>>(qkh, qkn, 0);
    mma_gemm<1,1><<<dim3(8, 128), 256, SMEM_GEMM>>>(
        qkn, fwqk, fbqk, nullptr, Q, Kl, MTOK, 2 * DD, INCC, DD, 0);

    // ---- s2: rw half1 chain ----
    cudaStreamWaitEvent(s2, evPrep, 0);
    cudaStreamWaitEvent(s2, evFold, 0);
    mma_gemm<0,0><<<dim3(5, 128), 256, SMEM_GEMM, s2>>>(
        xf, frw, rw_b, nullptr, qkh, nullptr, MTOK, INCC, INCC, INCC, MH);
    cudaEventRecord(evRW1, s2);
    ln_norm_h_kernel<640><<<MH / 8, 256, 0, s2>>>(qkh, qkn, MH);
    mma_gemm<1,1><<<dim3(8, 128), 256, SMEM_GEMM, s2>>>(
        qkn, fwqk, fbqk, nullptr, Q, Kl, MTOK, 2 * DD, INCC, DD, MH);
    cudaEventRecord(evQK1, s2);

    // ---- s1: kg chain ----
    cudaStreamWaitEvent(s1, evRW0, 0);
    cudaStreamWaitEvent(s1, evRW1, 0);
    dwconv_kernel<640,__half><<<dim3(5, BT * GG), 128, 0, s1>>>(qkh, ckT, convk_b, kg);
    ln_norm_kernel<640><<<(BT * NGLOB) / 8, 256, 0, s1>>>(kg, kgn);
    mma_gemm<2,0><<<dim3(4, 4), 256, SMEM_GEMM, s1>>>(
        kgn, fwqk + (size_t)DD * INCC, fbqk + DD, nullptr, Kg, nullptr,
        BT * NGLOB, DD, INCC, DD, 0);
    cudaEventRecord(evJoinKG, s1);

    // ---- parallel tail: each half = attention then out-projection, on its own stream ----
    cudaStreamWaitEvent(0, evJoinV, 0);
    cudaStreamWaitEvent(0, evJoinKG, 0);
    attn_kernel<<<BT * GG * NHEAD / 2, 256, ATTN_SMEM_BYTES>>>(Q, Kl, Kg, Vl, Vg, O, 0);
    mma_gemm<3,0><<<dim3(4, 128), 256, SMEM_GEMM>>>(
        O, fwo, bo, out, nullptr, nullptr, MTOK, DD, DD, DD, 0);

    cudaStreamWaitEvent(s2, evJoinV, 0);
    cudaStreamWaitEvent(s2, evJoinKG, 0);
    attn_kernel<<<BT * GG * NHEAD / 2, 256, ATTN_SMEM_BYTES, s2>>>(Q, Kl, Kg, Vl, Vg, O,
                                                                   BT * GG * NHEAD / 2);
    mma_gemm<3,0><<<dim3(4, 128), 256, SMEM_GEMM, s2>>>(
        O, fwo, bo, out, nullptr, nullptr, MTOK, DD, DD, DD, MH);
    cudaEventRecord(evEnd, s2);
    cudaStreamWaitEvent(0, evEnd, 0);

    cudaEventDestroy(evFork);
    cudaEventDestroy(evFold);
    cudaEventDestroy(evJoinV);
    cudaEventDestroy(evPrep);
    cudaEventDestroy(evRW0);
    cudaEventDestroy(evRW1);
    cudaEventDestroy(evQK1);
    cudaEventDestroy(evJoinKG);
    cudaEventDestroy(evEnd);
    cudaStreamDestroy(s1);
    cudaStreamDestroy(s2);
}